// round 1
// baseline (speedup 1.0000x reference)
#include <cuda_runtime.h>
#include <math.h>

// Problem constants
static constexpr int M0 = 32768;    // B*N nodes at layer 0
static constexpr int E0 = 262144;   // B*N*DEG edges
static constexpr int D  = 128;      // hidden dim

// ---------------- device scratch (no allocations allowed) ----------------
__device__ float g_h[M0 * D];          // h = x @ W
__device__ float g_out[M0 * D];        // GAT accumulation output
__device__ float g_x[(M0 / 2) * D];    // pooled+BN activations (next-layer input)
__device__ float g_es[M0];
__device__ float g_ed[M0];
__device__ float g_self[M0];           // self logit, then exp(self - mx)
__device__ float g_den[M0];
__device__ unsigned g_mx[M0];          // encoded segment max
__device__ float g_elog[E0];           // edge logit, then exp(logit - mx)
__device__ int g_src[E0];
__device__ int g_dst[E0];
__device__ unsigned char g_mask[E0];
__device__ unsigned g_bitmap[E0];      // 1MB = 8,388,608 bits (enough for layer-1 dedupe keyspace)
__device__ float g_sum[D];
__device__ float g_sumsq[D];

// ---------------- helpers ----------------
__device__ __forceinline__ unsigned encf(float f) {
    unsigned u = __float_as_uint(f);
    return (u & 0x80000000u) ? ~u : (u | 0x80000000u);
}
__device__ __forceinline__ float decf(unsigned u) {
    return (u & 0x80000000u) ? __uint_as_float(u & 0x7fffffffu) : __uint_as_float(~u);
}
__device__ __forceinline__ float lrelu(float x) { return x > 0.f ? x : 0.2f * x; }

// ---------------- kernels ----------------

__global__ void init_edges_kernel(const int* __restrict__ ei) {
    int e = blockIdx.x * blockDim.x + threadIdx.x;
    if (e >= E0) return;
    int s = ei[e];
    int d = ei[E0 + e];
    g_src[e] = s;
    g_dst[e] = d;
    g_mask[e] = (s != d) ? 1 : 0;
}

// h = X @ W  (X: [M, FIN], W: [FIN, 128]) ; X == nullptr -> read g_x
template <int FIN>
__global__ void gemm_kernel(const float* __restrict__ Xp, const float* __restrict__ W, int M) {
    __shared__ float xs[32][FIN];
    const float* X = Xp ? Xp : g_x;
    int c = threadIdx.x;                // 0..127 (output column)
    int r0 = blockIdx.x * 32;
    for (int i = c; i < 32 * FIN; i += 128) {
        int rr = i / FIN, kk = i % FIN;
        xs[rr][kk] = X[(r0 + rr) * FIN + kk];
    }
    __syncthreads();
    float acc[32];
#pragma unroll
    for (int r = 0; r < 32; r++) acc[r] = 0.f;
    for (int k = 0; k < FIN; k++) {
        float w = W[k * 128 + c];
#pragma unroll
        for (int r = 0; r < 32; r++) acc[r] += xs[r][k] * w;
    }
#pragma unroll
    for (int r = 0; r < 32; r++) g_h[(r0 + r) * 128 + c] = acc[r];
}

// per-node: es, ed, self logit, init segment max
__global__ void att_kernel(const float* __restrict__ a_s, const float* __restrict__ a_d, int M) {
    int gw = (blockIdx.x * blockDim.x + threadIdx.x) >> 5;
    int lane = threadIdx.x & 31;
    if (gw >= M) return;
    const float* h = g_h + gw * 128;
    float s = 0.f, d = 0.f;
#pragma unroll
    for (int i = lane; i < 128; i += 32) {
        float v = h[i];
        s += v * a_s[i];
        d += v * a_d[i];
    }
#pragma unroll
    for (int o = 16; o; o >>= 1) {
        s += __shfl_down_sync(0xffffffffu, s, o);
        d += __shfl_down_sync(0xffffffffu, d, o);
    }
    if (lane == 0) {
        g_es[gw] = s;
        g_ed[gw] = d;
        float l = lrelu(s + d);   // self-loop logit
        g_self[gw] = l;
        g_mx[gw] = encf(l);
    }
}

__global__ void edgemax_kernel() {
    int e = blockIdx.x * blockDim.x + threadIdx.x;
    if (e >= E0 || !g_mask[e]) return;
    int s = g_src[e], d = g_dst[e];
    float lg = lrelu(g_es[s] + g_ed[d]);
    g_elog[e] = lg;
    atomicMax(&g_mx[d], encf(lg));
}

__global__ void deninit_kernel(int M) {
    int i = blockIdx.x * blockDim.x + threadIdx.x;
    if (i >= M) return;
    float m = decf(g_mx[i]);
    float ex = expf(g_self[i] - m);
    g_self[i] = ex;   // now holds exp(self - mx)
    g_den[i] = ex;
    if (i < D) { g_sum[i] = 0.f; g_sumsq[i] = 0.f; }
}

__global__ void edgeexp_kernel() {
    int e = blockIdx.x * blockDim.x + threadIdx.x;
    if (e >= E0 || !g_mask[e]) return;
    int d = g_dst[e];
    float ex = expf(g_elog[e] - decf(g_mx[d]));
    g_elog[e] = ex;
    atomicAdd(&g_den[d], ex);
}

// out[i,:] = (exp_self/den) * h[i,:] + bias
__global__ void selfout_kernel(const float* __restrict__ bias, int M) {
    int idx = blockIdx.x * blockDim.x + threadIdx.x;
    if (idx >= M * 128) return;
    int i = idx >> 7, c = idx & 127;
    g_out[idx] = (g_self[i] / g_den[i]) * g_h[idx] + bias[c];
}

// warp per edge: out[d,:] += (ex/den[d]) * h[s,:]  via float4 atomics
__global__ void scatter_kernel() {
    int e = (blockIdx.x * blockDim.x + threadIdx.x) >> 5;
    int lane = threadIdx.x & 31;
    if (e >= E0 || !g_mask[e]) return;
    int s = g_src[e], d = g_dst[e];
    float w = g_elog[e] / g_den[d];
    const float4* hs = reinterpret_cast<const float4*>(g_h + s * 128);
    float4* od = reinterpret_cast<float4*>(g_out + d * 128);
    float4 v = hs[lane];
    float4 vv = make_float4(v.x * w, v.y * w, v.z * w, v.w * w);
    atomicAdd(&od[lane], vv);
}

// pooled[j,:] = relu(max(out[2j,:], out[2j+1,:])); accumulate BN stats
__global__ void pool_stats_kernel(int Mout) {
    int c = threadIdx.x;   // 0..127
    float s = 0.f, s2 = 0.f;
    for (int j = blockIdx.x; j < Mout; j += gridDim.x) {
        float a = g_out[(2 * j) * 128 + c];
        float b = g_out[(2 * j + 1) * 128 + c];
        float v = fmaxf(fmaxf(a, b), 0.f);
        g_x[j * 128 + c] = v;
        s += v;
        s2 += v * v;
    }
    atomicAdd(&g_sum[c], s);
    atomicAdd(&g_sumsq[c], s2);
}

// BN apply; write to d_out on last layer, else in-place on g_x
__global__ void bn_apply_kernel(int Mout, float* __restrict__ outp) {
    int idx = blockIdx.x * blockDim.x + threadIdx.x;
    if (idx >= Mout * 128) return;
    int c = idx & 127;
    float inv = 1.f / (float)Mout;
    float mu = g_sum[c] * inv;
    float var = g_sumsq[c] * inv - mu * mu;
    float v = (g_x[idx] - mu) * rsqrtf(var + 1e-5f);
    float* o = outp ? outp : g_x;
    o[idx] = v;
}

__global__ void bitclear_kernel(int words) {
    int i = blockIdx.x * blockDim.x + threadIdx.x;
    if (i < words) g_bitmap[i] = 0u;
}

// remap edges (>>1), drop self loops, dedupe by graph-local key bitmap
__global__ void remap_kernel(int NlOut) {
    int e = blockIdx.x * blockDim.x + threadIdx.x;
    if (e >= E0 || !g_mask[e]) return;
    int s = g_src[e] >> 1;
    int d = g_dst[e] >> 1;
    g_src[e] = s;
    g_dst[e] = d;
    if (s == d) { g_mask[e] = 0; return; }
    unsigned key = (unsigned)s * (unsigned)NlOut + (unsigned)(d & (NlOut - 1));
    unsigned bit = 1u << (key & 31);
    unsigned old = atomicOr(&g_bitmap[key >> 5], bit);
    if (old & bit) g_mask[e] = 0;
}

// ---------------- launch ----------------
extern "C" void kernel_launch(void* const* d_in, const int* in_sizes, int n_in,
                              void* d_out, int out_size) {
    const float* x    = (const float*)d_in[0];
    const float* W0   = (const float*)d_in[1];
    const float* W1   = (const float*)d_in[2];
    const float* W2   = (const float*)d_in[3];
    const float* as_  = (const float*)d_in[4];   // [3,128]
    const float* ad_  = (const float*)d_in[5];   // [3,128]
    const float* bias = (const float*)d_in[6];   // [3,128]
    const int*   ei   = (const int*)d_in[7];     // [2,E0]
    float* out = (float*)d_out;

    const float* W[3] = {W0, W1, W2};

    init_edges_kernel<<<E0 / 256, 256>>>(ei);

    int M = M0;
    for (int l = 0; l < 3; l++) {
        if (l == 0)
            gemm_kernel<64><<<M / 32, 128>>>(x, W[0], M);
        else
            gemm_kernel<128><<<M / 32, 128>>>(nullptr, W[l], M);

        att_kernel<<<M / 8, 256>>>(as_ + 128 * l, ad_ + 128 * l, M);
        edgemax_kernel<<<E0 / 256, 256>>>();
        deninit_kernel<<<M / 256, 256>>>(M);
        edgeexp_kernel<<<E0 / 256, 256>>>();
        selfout_kernel<<<(M * 128) / 256, 256>>>(bias + 128 * l, M);
        scatter_kernel<<<(E0 * 32) / 256, 256>>>();

        int Mout = M / 2;
        pool_stats_kernel<<<256, 128>>>(Mout);
        bn_apply_kernel<<<(Mout * 128) / 256, 256>>>(Mout, (l == 2) ? out : nullptr);

        if (l < 2) {
            int NlOut = (l == 0) ? 512 : 256;
            int words = (Mout * NlOut) >> 5;
            bitclear_kernel<<<(words + 255) / 256, 256>>>(words);
            remap_kernel<<<E0 / 256, 256>>>(NlOut);
        }
        M = Mout;
    }
}

// round 2
// speedup vs baseline: 1.0891x; 1.0891x over previous
#include <cuda_runtime.h>
#include <math.h>

static constexpr int M0 = 32768;    // B*N nodes at layer 0
static constexpr int E0 = 262144;   // B*N*DEG edges

// ---------------- device scratch ----------------
__device__ float g_h[M0 * 128];        // h = x @ W
__device__ float g_out[M0 * 128];      // GAT output rows (pre-bias, pre-relu)
__device__ float g_x[(M0 / 2) * 128];  // pooled+BN activations
__device__ float g_es[M0];
__device__ float g_ed[M0];
__device__ int g_src[E0];
__device__ int g_dst[E0];
__device__ unsigned char g_mask[E0];
__device__ int g_csr_src[E0];
__device__ int g_cnt[M0 + 1];
__device__ int g_off[M0 + 1];
__device__ int g_cur[M0];
__device__ unsigned g_bitmap[E0];      // 1 MB bitmap (covers layer-0 remap keyspace: 8.4M bits)
__device__ float g_sum[128];
__device__ float g_sumsq[128];

__device__ __forceinline__ float lrelu(float x) { return x > 0.f ? x : 0.2f * x; }

// ---------------- kernels ----------------

__global__ void clear_kernel(int nbitmap, int ncnt) {
    int i = blockIdx.x * blockDim.x + threadIdx.x;
    if (i < nbitmap) g_bitmap[i] = 0u;
    if (i < ncnt) g_cnt[i] = 0;
}

__global__ void init_edges_kernel(const int* __restrict__ ei) {
    int e = blockIdx.x * blockDim.x + threadIdx.x;
    if (e >= E0) return;
    int s = ei[e];
    int d = ei[E0 + e];
    g_src[e] = s;
    g_dst[e] = d;
    unsigned char m = (s != d) ? 1 : 0;
    g_mask[e] = m;
    if (m) atomicAdd(&g_cnt[d], 1);
}

// exclusive scan of g_cnt[0..n) -> g_off[0..n], also g_cur = g_off
__global__ void scan_kernel(int n) {
    __shared__ int partial[1024];
    int t = threadIdx.x;
    int c = (n + 1023) >> 10;
    int b = t * c;
    int e = min(b + c, n);
    int s = 0;
    for (int i = b; i < e; i++) s += g_cnt[i];
    partial[t] = s;
    __syncthreads();
    for (int off = 1; off < 1024; off <<= 1) {
        int v = (t >= off) ? partial[t - off] : 0;
        __syncthreads();
        partial[t] += v;
        __syncthreads();
    }
    int run = (t == 0) ? 0 : partial[t - 1];
    for (int i = b; i < e; i++) {
        g_off[i] = run;
        g_cur[i] = run;
        run += g_cnt[i];
    }
    if (e == n) g_off[n] = run;   // total (threads past the end write the same value)
}

__global__ void fill_kernel() {
    int e = blockIdx.x * blockDim.x + threadIdx.x;
    if (e >= E0 || !g_mask[e]) return;
    int pos = atomicAdd(&g_cur[g_dst[e]], 1);
    g_csr_src[pos] = g_src[e];
}

// h = X @ W  (X: [M, FIN], W: [FIN, 128]); Xp==nullptr -> g_x
// block: 256 threads (16x16), tile 128 rows x 128 cols, 8x8 micro-tile, K-chunk 16
template <int FIN>
__global__ void gemm_kernel(const float* __restrict__ Xp, const float* __restrict__ W) {
    __shared__ float Xt[16][132];   // transposed X tile: Xt[kk][r]
    __shared__ float Ws[16][128];
    const float* X = Xp ? Xp : g_x;
    int t = threadIdx.x;
    int tx = t & 15, ty = t >> 4;
    int r0 = blockIdx.x * 128;
    float acc[8][8];
#pragma unroll
    for (int i = 0; i < 8; i++)
#pragma unroll
        for (int j = 0; j < 8; j++) acc[i][j] = 0.f;

    for (int k0 = 0; k0 < FIN; k0 += 16) {
        // load X tile (128 rows x 16 k) transposed
#pragma unroll
        for (int i = 0; i < 8; i++) {
            int lin = t + 256 * i;          // 0..2047
            int kk = lin & 15, r = lin >> 4;
            Xt[kk][r] = X[(r0 + r) * FIN + k0 + kk];
        }
        // load W tile (16 k x 128 cols)
#pragma unroll
        for (int i = 0; i < 8; i++) {
            int lin = t + 256 * i;
            int c = lin & 127, kk = lin >> 7;
            Ws[kk][c] = W[(k0 + kk) * 128 + c];
        }
        __syncthreads();
#pragma unroll
        for (int kk = 0; kk < 16; kk++) {
            float4 a0 = *reinterpret_cast<const float4*>(&Xt[kk][ty * 8]);
            float4 a1 = *reinterpret_cast<const float4*>(&Xt[kk][ty * 8 + 4]);
            float4 b0 = *reinterpret_cast<const float4*>(&Ws[kk][tx * 8]);
            float4 b1 = *reinterpret_cast<const float4*>(&Ws[kk][tx * 8 + 4]);
            float a[8] = {a0.x, a0.y, a0.z, a0.w, a1.x, a1.y, a1.z, a1.w};
            float b[8] = {b0.x, b0.y, b0.z, b0.w, b1.x, b1.y, b1.z, b1.w};
#pragma unroll
            for (int i = 0; i < 8; i++)
#pragma unroll
                for (int j = 0; j < 8; j++) acc[i][j] += a[i] * b[j];
        }
        __syncthreads();
    }
#pragma unroll
    for (int i = 0; i < 8; i++) {
        int row = r0 + ty * 8 + i;
        float4 v0 = make_float4(acc[i][0], acc[i][1], acc[i][2], acc[i][3]);
        float4 v1 = make_float4(acc[i][4], acc[i][5], acc[i][6], acc[i][7]);
        *reinterpret_cast<float4*>(&g_h[row * 128 + tx * 8]) = v0;
        *reinterpret_cast<float4*>(&g_h[row * 128 + tx * 8 + 4]) = v1;
    }
}

// per-node attention terms; also clears BN stat accumulators for this layer
__global__ void att_kernel(const float* __restrict__ a_s, const float* __restrict__ a_d, int M) {
    int gid = blockIdx.x * blockDim.x + threadIdx.x;
    if (gid < 128) { g_sum[gid] = 0.f; g_sumsq[gid] = 0.f; }
    int gw = gid >> 5;
    int lane = threadIdx.x & 31;
    if (gw >= M) return;
    const float* h = g_h + gw * 128;
    float s = 0.f, d = 0.f;
#pragma unroll
    for (int i = lane; i < 128; i += 32) {
        float v = h[i];
        s += v * a_s[i];
        d += v * a_d[i];
    }
#pragma unroll
    for (int o = 16; o; o >>= 1) {
        s += __shfl_down_sync(0xffffffffu, s, o);
        d += __shfl_down_sync(0xffffffffu, d, o);
    }
    if (lane == 0) {
        g_es[gw] = s;
        g_ed[gw] = d;
    }
}

// warp per dst node: softmax over incoming edges + self loop, weighted sum of h rows
__global__ void aggregate_kernel(int M) {
    int w = (blockIdx.x * blockDim.x + threadIdx.x) >> 5;
    int lane = threadIdx.x & 31;
    if (w >= M) return;
    int base = g_off[w];
    int n = g_off[w + 1] - base;
    float ed_d = g_ed[w];
    float selflog = lrelu(g_es[w] + ed_d);
    float mx = selflog;
    for (int i = lane; i < n; i += 32)
        mx = fmaxf(mx, lrelu(g_es[g_csr_src[base + i]] + ed_d));
#pragma unroll
    for (int o = 16; o; o >>= 1) mx = fmaxf(mx, __shfl_xor_sync(0xffffffffu, mx, o));

    const float4* h4 = reinterpret_cast<const float4*>(g_h);
    float4 acc = make_float4(0.f, 0.f, 0.f, 0.f);
    float den = 0.f;
    for (int i = 0; i < n; i++) {
        int s = g_csr_src[base + i];
        float wt = expf(lrelu(g_es[s] + ed_d) - mx);
        den += wt;
        float4 hv = h4[s * 32 + lane];
        acc.x += wt * hv.x; acc.y += wt * hv.y; acc.z += wt * hv.z; acc.w += wt * hv.w;
    }
    float ws = expf(selflog - mx);
    den += ws;
    float4 hd = h4[w * 32 + lane];
    acc.x += ws * hd.x; acc.y += ws * hd.y; acc.z += ws * hd.z; acc.w += ws * hd.w;
    float inv = 1.f / den;
    float4 o = make_float4(acc.x * inv, acc.y * inv, acc.z * inv, acc.w * inv);
    reinterpret_cast<float4*>(g_out)[w * 32 + lane] = o;
}

// pooled[j,c] = relu(max(out[2j,c], out[2j+1,c]) + bias[c]); accumulate BN stats
__global__ void pool_stats_kernel(int Mout, const float* __restrict__ bias) {
    int c = threadIdx.x;   // 0..127
    float bc = bias[c];
    float s = 0.f, s2 = 0.f;
    for (int j = blockIdx.x; j < Mout; j += gridDim.x) {
        float a = g_out[(2 * j) * 128 + c];
        float b = g_out[(2 * j + 1) * 128 + c];
        float v = fmaxf(fmaxf(a, b) + bc, 0.f);
        g_x[j * 128 + c] = v;
        s += v;
        s2 += v * v;
    }
    atomicAdd(&g_sum[c], s);
    atomicAdd(&g_sumsq[c], s2);
}

__global__ void bn_apply_kernel(int Mout, float* __restrict__ outp) {
    int idx = blockIdx.x * blockDim.x + threadIdx.x;
    if (idx >= Mout * 128) return;
    int c = idx & 127;
    float inv = 1.f / (float)Mout;
    float mu = g_sum[c] * inv;
    float var = g_sumsq[c] * inv - mu * mu;
    float v = (g_x[idx] - mu) * rsqrtf(var + 1e-5f);
    float* o = outp ? outp : g_x;
    o[idx] = v;
}

// remap edges (>>1), drop self loops, dedupe via bitmap, count per new dst
__global__ void remap_kernel(int NlOut) {
    int e = blockIdx.x * blockDim.x + threadIdx.x;
    if (e >= E0 || !g_mask[e]) return;
    int s = g_src[e] >> 1;
    int d = g_dst[e] >> 1;
    g_src[e] = s;
    g_dst[e] = d;
    if (s == d) { g_mask[e] = 0; return; }
    unsigned key = (unsigned)s * (unsigned)NlOut + (unsigned)(d & (NlOut - 1));
    unsigned bit = 1u << (key & 31);
    unsigned old = atomicOr(&g_bitmap[key >> 5], bit);
    if (old & bit) { g_mask[e] = 0; return; }
    atomicAdd(&g_cnt[d], 1);
}

// ---------------- launch ----------------
extern "C" void kernel_launch(void* const* d_in, const int* in_sizes, int n_in,
                              void* d_out, int out_size) {
    const float* x    = (const float*)d_in[0];
    const float* W0   = (const float*)d_in[1];
    const float* W1   = (const float*)d_in[2];
    const float* W2   = (const float*)d_in[3];
    const float* as_  = (const float*)d_in[4];
    const float* ad_  = (const float*)d_in[5];
    const float* bias = (const float*)d_in[6];
    const int*   ei   = (const int*)d_in[7];
    float* out = (float*)d_out;

    const float* W[3] = {W0, W1, W2};

    // initial CSR build
    clear_kernel<<<(M0 + 256) / 256, 256>>>(0, M0 + 1);
    init_edges_kernel<<<E0 / 256, 256>>>(ei);
    scan_kernel<<<1, 1024>>>(M0);
    fill_kernel<<<E0 / 256, 256>>>();

    int M = M0;
    for (int l = 0; l < 3; l++) {
        if (l == 0)
            gemm_kernel<64><<<M / 128, 256>>>(x, W[0]);
        else
            gemm_kernel<128><<<M / 128, 256>>>(nullptr, W[l]);

        att_kernel<<<M / 8, 256>>>(as_ + 128 * l, ad_ + 128 * l, M);
        aggregate_kernel<<<M / 8, 256>>>(M);

        int Mout = M / 2;
        pool_stats_kernel<<<256, 128>>>(Mout, bias + 128 * l);
        bn_apply_kernel<<<(Mout * 128) / 256, 256>>>(Mout, (l == 2) ? out : nullptr);

        if (l < 2) {
            int NlOut = (l == 0) ? 512 : 256;
            int words = (Mout * NlOut) >> 5;   // bitmap words for key space
            int nclr = (words > Mout + 1) ? words : (Mout + 1);
            clear_kernel<<<(nclr + 255) / 256, 256>>>(words, Mout + 1);
            remap_kernel<<<E0 / 256, 256>>>(NlOut);
            scan_kernel<<<1, 1024>>>(Mout);
            fill_kernel<<<E0 / 256, 256>>>();
        }
        M = Mout;
    }
}

// round 3
// speedup vs baseline: 1.2094x; 1.1104x over previous
#include <cuda_runtime.h>
#include <math.h>

static constexpr int M0 = 32768;    // B*N nodes at layer 0
static constexpr int E0 = 262144;   // B*N*DEG edges

// ---------------- device scratch ----------------
__device__ float g_h[M0 * 128];        // h = x @ W
__device__ float g_x[(M0 / 2) * 128];  // pooled activations (pre-BN)
__device__ float g_es[M0];
__device__ float g_ed[M0];
__device__ int g_src[E0];
__device__ int g_dst[E0];
__device__ unsigned char g_mask[E0];
__device__ int g_csr_src[E0];
__device__ int g_cnt[M0 + 1];
__device__ int g_off[M0 + 1];
__device__ int g_cur[M0];
__device__ unsigned g_bitmap[E0];      // 1 MB bitmap (covers layer-0 remap keyspace)
__device__ float g_sum[3][128];        // per-layer BN stats
__device__ float g_sumsq[3][128];

__device__ __forceinline__ float lrelu(float x) { return x > 0.f ? x : 0.2f * x; }

// ---------------- CSR infrastructure ----------------

__global__ void clear0_kernel() {
    int i = blockIdx.x * blockDim.x + threadIdx.x;
    if (i < M0 + 1) g_cnt[i] = 0;
    if (i < 3 * 128) { (&g_sum[0][0])[i] = 0.f; (&g_sumsq[0][0])[i] = 0.f; }
}

__global__ void clear_kernel(int nbitmap, int ncnt) {
    int i = blockIdx.x * blockDim.x + threadIdx.x;
    if (i < nbitmap) g_bitmap[i] = 0u;
    if (i < ncnt) g_cnt[i] = 0;
}

__global__ void init_edges_kernel(const int* __restrict__ ei) {
    int e = blockIdx.x * blockDim.x + threadIdx.x;
    if (e >= E0) return;
    int s = ei[e];
    int d = ei[E0 + e];
    g_src[e] = s;
    g_dst[e] = d;
    unsigned char m = (s != d) ? 1 : 0;
    g_mask[e] = m;
    if (m) atomicAdd(&g_cnt[d], 1);
}

__global__ void scan_kernel(int n) {
    __shared__ int partial[1024];
    int t = threadIdx.x;
    int c = (n + 1023) >> 10;
    int b = t * c;
    int e = min(b + c, n);
    int s = 0;
    for (int i = b; i < e; i++) s += g_cnt[i];
    partial[t] = s;
    __syncthreads();
    for (int off = 1; off < 1024; off <<= 1) {
        int v = (t >= off) ? partial[t - off] : 0;
        __syncthreads();
        partial[t] += v;
        __syncthreads();
    }
    int run = (t == 0) ? 0 : partial[t - 1];
    for (int i = b; i < e; i++) {
        g_off[i] = run;
        g_cur[i] = run;
        run += g_cnt[i];
    }
    if (e == n) g_off[n] = run;
}

__global__ void fill_kernel() {
    int e = blockIdx.x * blockDim.x + threadIdx.x;
    if (e >= E0 || !g_mask[e]) return;
    int pos = atomicAdd(&g_cur[g_dst[e]], 1);
    g_csr_src[pos] = g_src[e];
}

__global__ void remap_kernel(int NlOut) {
    int e = blockIdx.x * blockDim.x + threadIdx.x;
    if (e >= E0 || !g_mask[e]) return;
    int s = g_src[e] >> 1;
    int d = g_dst[e] >> 1;
    g_src[e] = s;
    g_dst[e] = d;
    if (s == d) { g_mask[e] = 0; return; }
    unsigned key = (unsigned)s * (unsigned)NlOut + (unsigned)(d & (NlOut - 1));
    unsigned bit = 1u << (key & 31);
    unsigned old = atomicOr(&g_bitmap[key >> 5], bit);
    if (old & bit) { g_mask[e] = 0; return; }
    atomicAdd(&g_cnt[d], 1);
}

// ---------------- fused GEMM (+BN-on-load, +attention epilogue) ----------------
// h = norm(X) @ W, es = h@a_s, ed = h@a_d
// block 256 (16x16), tile 128x128, 8x8 micro-tile
template <int FIN, bool DO_BN>
__global__ void gemm_att_kernel(const float* __restrict__ Xp, const float* __restrict__ W,
                                const float* __restrict__ a_s, const float* __restrict__ a_d,
                                const float* __restrict__ sums, const float* __restrict__ sumsq,
                                float inv_count) {
    __shared__ float Xt[16][132];      // Xt[kk][r]
    __shared__ float Ws[16][128];
    __shared__ float mu_s[FIN], is_s[FIN];
    __shared__ float red_s[128][17], red_d[128][17];
    const float* X = Xp ? Xp : g_x;
    int t = threadIdx.x;
    int tx = t & 15, ty = t >> 4;
    int r0 = blockIdx.x * 128;

    if (DO_BN) {
        if (t < FIN) {
            float mu = sums[t] * inv_count;
            float var = sumsq[t] * inv_count - mu * mu;
            mu_s[t] = mu;
            is_s[t] = rsqrtf(var + 1e-5f);
        }
        __syncthreads();
    }

    float acc[8][8];
#pragma unroll
    for (int i = 0; i < 8; i++)
#pragma unroll
        for (int j = 0; j < 8; j++) acc[i][j] = 0.f;

    for (int k0 = 0; k0 < FIN; k0 += 16) {
#pragma unroll
        for (int i = 0; i < 8; i++) {
            int lin = t + 256 * i;
            int kk = lin & 15, r = lin >> 4;
            float v = X[(r0 + r) * FIN + k0 + kk];
            if (DO_BN) v = (v - mu_s[k0 + kk]) * is_s[k0 + kk];
            Xt[kk][r] = v;
        }
#pragma unroll
        for (int i = 0; i < 8; i++) {
            int lin = t + 256 * i;
            int c = lin & 127, kk = lin >> 7;
            Ws[kk][c] = W[(k0 + kk) * 128 + c];
        }
        __syncthreads();
#pragma unroll
        for (int kk = 0; kk < 16; kk++) {
            float4 a0 = *reinterpret_cast<const float4*>(&Xt[kk][ty * 8]);
            float4 a1 = *reinterpret_cast<const float4*>(&Xt[kk][ty * 8 + 4]);
            float4 b0 = *reinterpret_cast<const float4*>(&Ws[kk][tx * 8]);
            float4 b1 = *reinterpret_cast<const float4*>(&Ws[kk][tx * 8 + 4]);
            float a[8] = {a0.x, a0.y, a0.z, a0.w, a1.x, a1.y, a1.z, a1.w};
            float b[8] = {b0.x, b0.y, b0.z, b0.w, b1.x, b1.y, b1.z, b1.w};
#pragma unroll
            for (int i = 0; i < 8; i++)
#pragma unroll
                for (int j = 0; j < 8; j++) acc[i][j] += a[i] * b[j];
        }
        __syncthreads();
    }

    // write h + attention partial reduction
    float4 asv0 = *reinterpret_cast<const float4*>(&a_s[tx * 8]);
    float4 asv1 = *reinterpret_cast<const float4*>(&a_s[tx * 8 + 4]);
    float4 adv0 = *reinterpret_cast<const float4*>(&a_d[tx * 8]);
    float4 adv1 = *reinterpret_cast<const float4*>(&a_d[tx * 8 + 4]);
    float asr[8] = {asv0.x, asv0.y, asv0.z, asv0.w, asv1.x, asv1.y, asv1.z, asv1.w};
    float adr[8] = {adv0.x, adv0.y, adv0.z, adv0.w, adv1.x, adv1.y, adv1.z, adv1.w};
#pragma unroll
    for (int i = 0; i < 8; i++) {
        int row = ty * 8 + i;
        float4 v0 = make_float4(acc[i][0], acc[i][1], acc[i][2], acc[i][3]);
        float4 v1 = make_float4(acc[i][4], acc[i][5], acc[i][6], acc[i][7]);
        *reinterpret_cast<float4*>(&g_h[(r0 + row) * 128 + tx * 8]) = v0;
        *reinterpret_cast<float4*>(&g_h[(r0 + row) * 128 + tx * 8 + 4]) = v1;
        float ps = 0.f, pd = 0.f;
#pragma unroll
        for (int j = 0; j < 8; j++) { ps += acc[i][j] * asr[j]; pd += acc[i][j] * adr[j]; }
        red_s[row][tx] = ps;
        red_d[row][tx] = pd;
    }
    __syncthreads();
    if (t < 128) {
        float s = 0.f, d = 0.f;
#pragma unroll
        for (int k = 0; k < 16; k++) { s += red_s[t][k]; d += red_d[t][k]; }
        g_es[r0 + t] = s;
        g_ed[r0 + t] = d;
    }
}

// ---------------- fused aggregate + pool + bias + relu + BN stats ----------------
// 8 warps/block, warp per dst node; pairs (2j, 2j+1) pooled in-block.
__global__ void aggregate_pool_kernel(int M, const float* __restrict__ bias,
                                      float* __restrict__ sums, float* __restrict__ sumsq) {
    __shared__ float4 buf[4][32];
    __shared__ float ssum[128], ssq[128];
    int t = threadIdx.x;
    int wp = t >> 5;           // 0..7
    int lane = t & 31;
    if (t < 128) { ssum[t] = 0.f; ssq[t] = 0.f; }
    int w = blockIdx.x * 8 + wp;

    float4 o = make_float4(0.f, 0.f, 0.f, 0.f);
    {
        int base = g_off[w];
        int n = g_off[w + 1] - base;
        float ed_d = g_ed[w];
        float selflog = lrelu(g_es[w] + ed_d);
        float mx = selflog;
        for (int i = lane; i < n; i += 32)
            mx = fmaxf(mx, lrelu(g_es[g_csr_src[base + i]] + ed_d));
#pragma unroll
        for (int off = 16; off; off >>= 1) mx = fmaxf(mx, __shfl_xor_sync(0xffffffffu, mx, off));

        const float4* h4 = reinterpret_cast<const float4*>(g_h);
        float den = 0.f;
        for (int i = 0; i < n; i++) {
            int s = g_csr_src[base + i];
            float wt = __expf(lrelu(g_es[s] + ed_d) - mx);
            den += wt;
            float4 hv = h4[s * 32 + lane];
            o.x += wt * hv.x; o.y += wt * hv.y; o.z += wt * hv.z; o.w += wt * hv.w;
        }
        float ws = __expf(selflog - mx);
        den += ws;
        float4 hd = h4[w * 32 + lane];
        o.x += ws * hd.x; o.y += ws * hd.y; o.z += ws * hd.z; o.w += ws * hd.w;
        float inv = 1.f / den;
        o.x *= inv; o.y *= inv; o.z *= inv; o.w *= inv;
    }
    // even warps deposit rows; odd warps pool
    if (!(wp & 1)) buf[wp >> 1][lane] = o;
    __syncthreads();
    if (wp & 1) {
        float4 a = buf[wp >> 1][lane];
        float4 bv = reinterpret_cast<const float4*>(bias)[lane];
        float4 v;
        v.x = fmaxf(fmaxf(a.x, o.x) + bv.x, 0.f);
        v.y = fmaxf(fmaxf(a.y, o.y) + bv.y, 0.f);
        v.z = fmaxf(fmaxf(a.z, o.z) + bv.z, 0.f);
        v.w = fmaxf(fmaxf(a.w, o.w) + bv.w, 0.f);
        int j = blockIdx.x * 4 + (wp >> 1);
        reinterpret_cast<float4*>(g_x)[j * 32 + lane] = v;
        int c = lane * 4;
        atomicAdd(&ssum[c], v.x);     atomicAdd(&ssq[c], v.x * v.x);
        atomicAdd(&ssum[c + 1], v.y); atomicAdd(&ssq[c + 1], v.y * v.y);
        atomicAdd(&ssum[c + 2], v.z); atomicAdd(&ssq[c + 2], v.z * v.z);
        atomicAdd(&ssum[c + 3], v.w); atomicAdd(&ssq[c + 3], v.w * v.w);
    }
    __syncthreads();
    if (t < 128) {
        atomicAdd(&sums[t], ssum[t]);
        atomicAdd(&sumsq[t], ssq[t]);
    }
}

__global__ void bn_apply_kernel(int Mout, float* __restrict__ outp,
                                const float* __restrict__ sums, const float* __restrict__ sumsq) {
    int idx = blockIdx.x * blockDim.x + threadIdx.x;
    if (idx >= Mout * 128) return;
    int c = idx & 127;
    float inv = 1.f / (float)Mout;
    float mu = sums[c] * inv;
    float var = sumsq[c] * inv - mu * mu;
    outp[idx] = (g_x[idx] - mu) * rsqrtf(var + 1e-5f);
}

// ---------------- launch ----------------
extern "C" void kernel_launch(void* const* d_in, const int* in_sizes, int n_in,
                              void* d_out, int out_size) {
    const float* x    = (const float*)d_in[0];
    const float* W0   = (const float*)d_in[1];
    const float* W1   = (const float*)d_in[2];
    const float* W2   = (const float*)d_in[3];
    const float* as_  = (const float*)d_in[4];
    const float* ad_  = (const float*)d_in[5];
    const float* bias = (const float*)d_in[6];
    const int*   ei   = (const int*)d_in[7];
    float* out = (float*)d_out;

    float* sum_p; float* ssq_p;
    cudaGetSymbolAddress((void**)&sum_p, g_sum);
    cudaGetSymbolAddress((void**)&ssq_p, g_sumsq);

    // CSR build for layer 0 + stat zeroing
    clear0_kernel<<<(M0 + 256) / 256, 256>>>();
    init_edges_kernel<<<E0 / 256, 256>>>(ei);
    scan_kernel<<<1, 1024>>>(M0);
    fill_kernel<<<E0 / 256, 256>>>();

    // layer 0
    gemm_att_kernel<64, false><<<M0 / 128, 256>>>(x, W0, as_, ad_, nullptr, nullptr, 0.f);
    aggregate_pool_kernel<<<M0 / 8, 256>>>(M0, bias, sum_p, ssq_p);

    // CSR rebuild for layer 1
    {
        int words = (16384 * 512) >> 5;   // 262144
        clear_kernel<<<(words + 255) / 256, 256>>>(words, 16385);
        remap_kernel<<<E0 / 256, 256>>>(512);
        scan_kernel<<<1, 1024>>>(16384);
        fill_kernel<<<E0 / 256, 256>>>();
    }

    // layer 1 (input: g_x 16384 rows, BN with slot 0)
    gemm_att_kernel<128, true><<<16384 / 128, 256>>>(nullptr, W1, as_ + 128, ad_ + 128,
                                                     sum_p, ssq_p, 1.f / 16384.f);
    aggregate_pool_kernel<<<16384 / 8, 256>>>(16384, bias + 128, sum_p + 128, ssq_p + 128);

    // CSR rebuild for layer 2
    {
        int words = (8192 * 256) >> 5;    // 65536
        clear_kernel<<<(words + 255) / 256, 256>>>(words, 8193);
        remap_kernel<<<E0 / 256, 256>>>(256);
        scan_kernel<<<1, 1024>>>(8192);
        fill_kernel<<<E0 / 256, 256>>>();
    }

    // layer 2 (input: g_x 8192 rows, BN with slot 1)
    gemm_att_kernel<128, true><<<8192 / 128, 256>>>(nullptr, W2, as_ + 256, ad_ + 256,
                                                    sum_p + 128, ssq_p + 128, 1.f / 8192.f);
    aggregate_pool_kernel<<<8192 / 8, 256>>>(8192, bias + 256, sum_p + 256, ssq_p + 256);

    // final BN -> output
    bn_apply_kernel<<<(4096 * 128) / 256, 256>>>(4096, out, sum_p + 256, ssq_p + 256);
}

// round 4
// speedup vs baseline: 2.2236x; 1.8386x over previous
#include <cuda_runtime.h>
#include <math.h>

static constexpr int M0 = 32768;     // B*N nodes at layer 0
static constexpr int E0 = 262144;    // edges
static constexpr int CAP = 96;       // bucket capacity (max in-degree ~55 at layer 2)
static constexpr int CNT_TOT = M0 + M0 / 2 + M0 / 4;           // 57344
static constexpr int BM0_WORDS = (16384 * 512) / 32;           // layer-1 dedupe bitmap: 262144
static constexpr int BM1_WORDS = (8192 * 256) / 32;            // layer-2 dedupe bitmap: 65536
static constexpr int BM_TOT = BM0_WORDS + BM1_WORDS;           // 327680

// ---------------- device scratch ----------------
__device__ float g_h[M0 * 128];
__device__ float g_x[(M0 / 2) * 128];
__device__ float g_es[M0];
__device__ float g_ed[M0];
__device__ int g_adj[CNT_TOT * CAP];    // bucketed adjacency for all 3 layers
__device__ int g_cnt[CNT_TOT];
__device__ unsigned g_bitmap[BM_TOT];
__device__ float g_sum[3][128];
__device__ float g_sumsq[3][128];

__device__ __forceinline__ float lrelu(float x) { return x > 0.f ? x : 0.2f * x; }

// ---------------- setup ----------------

__global__ void clear_kernel() {
    int i = blockIdx.x * blockDim.x + threadIdx.x;
    if (i < BM_TOT) g_bitmap[i] = 0u;
    if (i < CNT_TOT) g_cnt[i] = 0;
    if (i < 3 * 128) { (&g_sum[0][0])[i] = 0.f; (&g_sumsq[0][0])[i] = 0.f; }
}

// one pass: build adjacency buckets for ALL THREE layers from the raw edge list.
// layer0: all edges with s!=d (duplicates kept).
// layer1: distinct (s>>1, d>>1) with s1!=d1.
// layer2: distinct (s>>2, d>>2) with s2!=d2 (dedupe commutes with pooling).
__global__ void build_csr_kernel(const int* __restrict__ ei) {
    int e = blockIdx.x * blockDim.x + threadIdx.x;
    if (e >= E0) return;
    int s0 = ei[e];
    int d0 = ei[E0 + e];
    if (s0 == d0) return;
    // layer 0
    int p = atomicAdd(&g_cnt[d0], 1);
    if (p < CAP) g_adj[d0 * CAP + p] = s0;
    // layer 1
    int s1 = s0 >> 1, d1 = d0 >> 1;
    if (s1 == d1) return;   // maps to self-loop at every deeper level too
    unsigned key1 = (unsigned)s1 * 512u + (unsigned)(d1 & 511);
    unsigned bit1 = 1u << (key1 & 31);
    if (!(atomicOr(&g_bitmap[key1 >> 5], bit1) & bit1)) {
        p = atomicAdd(&g_cnt[M0 + d1], 1);
        if (p < CAP) g_adj[(M0 + d1) * CAP + p] = s1;
    }
    // layer 2
    int s2 = s1 >> 1, d2 = d1 >> 1;
    if (s2 == d2) return;
    unsigned key2 = (unsigned)s2 * 256u + (unsigned)(d2 & 255);
    unsigned bit2 = 1u << (key2 & 31);
    if (!(atomicOr(&g_bitmap[BM0_WORDS + (key2 >> 5)], bit2) & bit2)) {
        p = atomicAdd(&g_cnt[M0 + M0 / 2 + d2], 1);
        if (p < CAP) g_adj[(M0 + M0 / 2 + d2) * CAP + p] = s2;
    }
}

// ---------------- fused GEMM (+BN-on-load, +attention epilogue) ----------------
template <int FIN, bool DO_BN>
__global__ void gemm_att_kernel(const float* __restrict__ Xp, const float* __restrict__ W,
                                const float* __restrict__ a_s, const float* __restrict__ a_d,
                                const float* __restrict__ sums, const float* __restrict__ sumsq,
                                float inv_count) {
    __shared__ float Xt[16][132];
    __shared__ float Ws[16][128];
    __shared__ float mu_s[FIN], is_s[FIN];
    __shared__ float red_s[128][17], red_d[128][17];
    const float* X = Xp ? Xp : g_x;
    int t = threadIdx.x;
    int tx = t & 15, ty = t >> 4;
    int r0 = blockIdx.x * 128;

    if (DO_BN) {
        if (t < FIN) {
            float mu = sums[t] * inv_count;
            float var = sumsq[t] * inv_count - mu * mu;
            mu_s[t] = mu;
            is_s[t] = rsqrtf(var + 1e-5f);
        }
        __syncthreads();
    }

    float acc[8][8];
#pragma unroll
    for (int i = 0; i < 8; i++)
#pragma unroll
        for (int j = 0; j < 8; j++) acc[i][j] = 0.f;

    for (int k0 = 0; k0 < FIN; k0 += 16) {
#pragma unroll
        for (int i = 0; i < 8; i++) {
            int lin = t + 256 * i;
            int kk = lin & 15, r = lin >> 4;
            float v = X[(r0 + r) * FIN + k0 + kk];
            if (DO_BN) v = (v - mu_s[k0 + kk]) * is_s[k0 + kk];
            Xt[kk][r] = v;
        }
#pragma unroll
        for (int i = 0; i < 8; i++) {
            int lin = t + 256 * i;
            int c = lin & 127, kk = lin >> 7;
            Ws[kk][c] = W[(k0 + kk) * 128 + c];
        }
        __syncthreads();
#pragma unroll
        for (int kk = 0; kk < 16; kk++) {
            float4 a0 = *reinterpret_cast<const float4*>(&Xt[kk][ty * 8]);
            float4 a1 = *reinterpret_cast<const float4*>(&Xt[kk][ty * 8 + 4]);
            float4 b0 = *reinterpret_cast<const float4*>(&Ws[kk][tx * 8]);
            float4 b1 = *reinterpret_cast<const float4*>(&Ws[kk][tx * 8 + 4]);
            float a[8] = {a0.x, a0.y, a0.z, a0.w, a1.x, a1.y, a1.z, a1.w};
            float b[8] = {b0.x, b0.y, b0.z, b0.w, b1.x, b1.y, b1.z, b1.w};
#pragma unroll
            for (int i = 0; i < 8; i++)
#pragma unroll
                for (int j = 0; j < 8; j++) acc[i][j] += a[i] * b[j];
        }
        __syncthreads();
    }

    float4 asv0 = *reinterpret_cast<const float4*>(&a_s[tx * 8]);
    float4 asv1 = *reinterpret_cast<const float4*>(&a_s[tx * 8 + 4]);
    float4 adv0 = *reinterpret_cast<const float4*>(&a_d[tx * 8]);
    float4 adv1 = *reinterpret_cast<const float4*>(&a_d[tx * 8 + 4]);
    float asr[8] = {asv0.x, asv0.y, asv0.z, asv0.w, asv1.x, asv1.y, asv1.z, asv1.w};
    float adr[8] = {adv0.x, adv0.y, adv0.z, adv0.w, adv1.x, adv1.y, adv1.z, adv1.w};
#pragma unroll
    for (int i = 0; i < 8; i++) {
        int row = ty * 8 + i;
        float4 v0 = make_float4(acc[i][0], acc[i][1], acc[i][2], acc[i][3]);
        float4 v1 = make_float4(acc[i][4], acc[i][5], acc[i][6], acc[i][7]);
        *reinterpret_cast<float4*>(&g_h[(r0 + row) * 128 + tx * 8]) = v0;
        *reinterpret_cast<float4*>(&g_h[(r0 + row) * 128 + tx * 8 + 4]) = v1;
        float ps = 0.f, pd = 0.f;
#pragma unroll
        for (int j = 0; j < 8; j++) { ps += acc[i][j] * asr[j]; pd += acc[i][j] * adr[j]; }
        red_s[row][tx] = ps;
        red_d[row][tx] = pd;
    }
    __syncthreads();
    if (t < 128) {
        float s = 0.f, d = 0.f;
#pragma unroll
        for (int k = 0; k < 16; k++) { s += red_s[t][k]; d += red_d[t][k]; }
        g_es[r0 + t] = s;
        g_ed[r0 + t] = d;
    }
}

// ---------------- fused aggregate + pool + bias + relu + BN stats ----------------
// warp per dst node; lane-parallel logits + shfl-broadcast gather; warp pairs pool.
__global__ void aggregate_pool_kernel(int cbase, const float* __restrict__ bias,
                                      float* __restrict__ sums, float* __restrict__ sumsq) {
    __shared__ float4 buf[4][32];
    __shared__ float ssum[128], ssq[128];
    int t = threadIdx.x;
    int wp = t >> 5;
    int lane = t & 31;
    if (t < 128) { ssum[t] = 0.f; ssq[t] = 0.f; }
    int w = blockIdx.x * 8 + wp;

    int n = min(g_cnt[cbase + w], CAP);
    int base = (cbase + w) * CAP;
    float ed_d = g_ed[w];
    float selflog = lrelu(g_es[w] + ed_d);

    // lane-parallel logits (chunk 0 cached in registers)
    int s0 = 0;
    float lg0 = -1e30f;
    if (lane < n) {
        s0 = g_adj[base + lane];
        lg0 = lrelu(g_es[s0] + ed_d);
    }
    float mx = fmaxf(selflog, lg0);
    for (int c = 32; c < n; c += 32) {
        if (c + lane < n) {
            int s = g_adj[base + c + lane];
            mx = fmaxf(mx, lrelu(g_es[s] + ed_d));
        }
    }
#pragma unroll
    for (int o = 16; o; o >>= 1) mx = fmaxf(mx, __shfl_xor_sync(0xffffffffu, mx, o));

    const float4* h4 = reinterpret_cast<const float4*>(g_h);
    float ws = __expf(selflog - mx);
    float4 hd = h4[w * 32 + lane];
    float4 acc = make_float4(ws * hd.x, ws * hd.y, ws * hd.z, ws * hd.w);

    float den_l = 0.f;
    // chunk 0 (cached)
    {
        float wt0 = (lane < n) ? __expf(lg0 - mx) : 0.f;
        den_l += wt0;
        int m = min(n, 32);
#pragma unroll 4
        for (int j = 0; j < m; j++) {
            int s = __shfl_sync(0xffffffffu, s0, j);
            float wv = __shfl_sync(0xffffffffu, wt0, j);
            float4 hv = h4[s * 32 + lane];
            acc.x += wv * hv.x; acc.y += wv * hv.y; acc.z += wv * hv.z; acc.w += wv * hv.w;
        }
    }
    // remaining chunks (rare: only when n > 32)
    for (int c = 32; c < n; c += 32) {
        int sl = 0;
        float wtl = 0.f;
        if (c + lane < n) {
            sl = g_adj[base + c + lane];
            wtl = __expf(lrelu(g_es[sl] + ed_d) - mx);
        }
        den_l += wtl;
        int m = min(n - c, 32);
#pragma unroll 4
        for (int j = 0; j < m; j++) {
            int s = __shfl_sync(0xffffffffu, sl, j);
            float wv = __shfl_sync(0xffffffffu, wtl, j);
            float4 hv = h4[s * 32 + lane];
            acc.x += wv * hv.x; acc.y += wv * hv.y; acc.z += wv * hv.z; acc.w += wv * hv.w;
        }
    }
#pragma unroll
    for (int o = 16; o; o >>= 1) den_l += __shfl_xor_sync(0xffffffffu, den_l, o);
    float inv = 1.f / (den_l + ws);
    acc.x *= inv; acc.y *= inv; acc.z *= inv; acc.w *= inv;

    // pool pairs (even warp deposits, odd warp combines)
    if (!(wp & 1)) buf[wp >> 1][lane] = acc;
    __syncthreads();
    if (wp & 1) {
        float4 a = buf[wp >> 1][lane];
        float4 bv = reinterpret_cast<const float4*>(bias)[lane];
        float4 v;
        v.x = fmaxf(fmaxf(a.x, acc.x) + bv.x, 0.f);
        v.y = fmaxf(fmaxf(a.y, acc.y) + bv.y, 0.f);
        v.z = fmaxf(fmaxf(a.z, acc.z) + bv.z, 0.f);
        v.w = fmaxf(fmaxf(a.w, acc.w) + bv.w, 0.f);
        int j = blockIdx.x * 4 + (wp >> 1);
        reinterpret_cast<float4*>(g_x)[j * 32 + lane] = v;
        int c = lane * 4;
        atomicAdd(&ssum[c], v.x);     atomicAdd(&ssq[c], v.x * v.x);
        atomicAdd(&ssum[c + 1], v.y); atomicAdd(&ssq[c + 1], v.y * v.y);
        atomicAdd(&ssum[c + 2], v.z); atomicAdd(&ssq[c + 2], v.z * v.z);
        atomicAdd(&ssum[c + 3], v.w); atomicAdd(&ssq[c + 3], v.w * v.w);
    }
    __syncthreads();
    if (t < 128) {
        atomicAdd(&sums[t], ssum[t]);
        atomicAdd(&sumsq[t], ssq[t]);
    }
}

__global__ void bn_apply_kernel(int Mout, float* __restrict__ outp,
                                const float* __restrict__ sums, const float* __restrict__ sumsq) {
    int idx = blockIdx.x * blockDim.x + threadIdx.x;
    if (idx >= Mout * 128) return;
    int c = idx & 127;
    float inv = 1.f / (float)Mout;
    float mu = sums[c] * inv;
    float var = sumsq[c] * inv - mu * mu;
    outp[idx] = (g_x[idx] - mu) * rsqrtf(var + 1e-5f);
}

// ---------------- launch ----------------
extern "C" void kernel_launch(void* const* d_in, const int* in_sizes, int n_in,
                              void* d_out, int out_size) {
    const float* x    = (const float*)d_in[0];
    const float* W0   = (const float*)d_in[1];
    const float* W1   = (const float*)d_in[2];
    const float* W2   = (const float*)d_in[3];
    const float* as_  = (const float*)d_in[4];
    const float* ad_  = (const float*)d_in[5];
    const float* bias = (const float*)d_in[6];
    const int*   ei   = (const int*)d_in[7];
    float* out = (float*)d_out;

    float* sum_p; float* ssq_p;
    cudaGetSymbolAddress((void**)&sum_p, g_sum);
    cudaGetSymbolAddress((void**)&ssq_p, g_sumsq);

    clear_kernel<<<(BM_TOT + 255) / 256, 256>>>();
    build_csr_kernel<<<E0 / 256, 256>>>(ei);

    // layer 0
    gemm_att_kernel<64, false><<<M0 / 128, 256>>>(x, W0, as_, ad_, nullptr, nullptr, 0.f);
    aggregate_pool_kernel<<<M0 / 8, 256>>>(0, bias, sum_p, ssq_p);

    // layer 1
    gemm_att_kernel<128, true><<<16384 / 128, 256>>>(nullptr, W1, as_ + 128, ad_ + 128,
                                                     sum_p, ssq_p, 1.f / 16384.f);
    aggregate_pool_kernel<<<16384 / 8, 256>>>(M0, bias + 128, sum_p + 128, ssq_p + 128);

    // layer 2
    gemm_att_kernel<128, true><<<8192 / 128, 256>>>(nullptr, W2, as_ + 256, ad_ + 256,
                                                    sum_p + 128, ssq_p + 128, 1.f / 8192.f);
    aggregate_pool_kernel<<<8192 / 8, 256>>>(M0 + M0 / 2, bias + 256, sum_p + 256, ssq_p + 256);

    // final BN -> output
    bn_apply_kernel<<<(4096 * 128) / 256, 256>>>(4096, out, sum_p + 256, ssq_p + 256);
}

// round 5
// speedup vs baseline: 2.2353x; 1.0053x over previous
#include <cuda_runtime.h>
#include <math.h>

static constexpr int M0 = 32768;     // B*N nodes at layer 0
static constexpr int E0 = 262144;    // edges
static constexpr int CAP = 96;       // bucket capacity (max in-degree ~55 at layer 2)
static constexpr int CNT_TOT = M0 + M0 / 2 + M0 / 4;           // 57344
static constexpr int BM0_WORDS = (16384 * 512) / 32;           // 262144
static constexpr int BM1_WORDS = (8192 * 256) / 32;            // 65536
static constexpr int BM_TOT = BM0_WORDS + BM1_WORDS;           // 327680

// ---------------- device scratch ----------------
__device__ float g_h[M0 * 128];
__device__ float g_x[(M0 / 2) * 128];
__device__ float g_es[M0];
__device__ float g_ed[M0];
__device__ int g_adj[CNT_TOT * CAP];
__device__ int g_cnt[CNT_TOT];
__device__ unsigned g_bitmap[BM_TOT];
__device__ float g_sum[3][128];
__device__ float g_sumsq[3][128];

__device__ __forceinline__ float lrelu(float x) { return x > 0.f ? x : 0.2f * x; }

// ---------------- setup ----------------

__global__ void clear_kernel() {
    int i = blockIdx.x * blockDim.x + threadIdx.x;
    if (i < BM_TOT) g_bitmap[i] = 0u;
    if (i < CNT_TOT) g_cnt[i] = 0;
    if (i < 3 * 128) { (&g_sum[0][0])[i] = 0.f; (&g_sumsq[0][0])[i] = 0.f; }
}

// build adjacency buckets for all three layers in one pass (dedupe commutes with pooling)
__global__ void build_csr_kernel(const int* __restrict__ ei) {
    int e = blockIdx.x * blockDim.x + threadIdx.x;
    if (e >= E0) return;
    int s0 = ei[e];
    int d0 = ei[E0 + e];
    if (s0 == d0) return;
    int p = atomicAdd(&g_cnt[d0], 1);
    if (p < CAP) g_adj[d0 * CAP + p] = s0;
    int s1 = s0 >> 1, d1 = d0 >> 1;
    if (s1 == d1) return;
    unsigned key1 = (unsigned)s1 * 512u + (unsigned)(d1 & 511);
    unsigned bit1 = 1u << (key1 & 31);
    if (!(atomicOr(&g_bitmap[key1 >> 5], bit1) & bit1)) {
        p = atomicAdd(&g_cnt[M0 + d1], 1);
        if (p < CAP) g_adj[(M0 + d1) * CAP + p] = s1;
    }
    int s2 = s1 >> 1, d2 = d1 >> 1;
    if (s2 == d2) return;
    unsigned key2 = (unsigned)s2 * 256u + (unsigned)(d2 & 255);
    unsigned bit2 = 1u << (key2 & 31);
    if (!(atomicOr(&g_bitmap[BM0_WORDS + (key2 >> 5)], bit2) & bit2)) {
        p = atomicAdd(&g_cnt[M0 + M0 / 2 + d2], 1);
        if (p < CAP) g_adj[(M0 + M0 / 2 + d2) * CAP + p] = s2;
    }
}

// ---------------- fused GEMM (+BN-on-load, +attention epilogue) ----------------
template <int FIN, bool DO_BN>
__global__ void gemm_att_kernel(const float* __restrict__ Xp, const float* __restrict__ W,
                                const float* __restrict__ a_s, const float* __restrict__ a_d,
                                const float* __restrict__ sums, const float* __restrict__ sumsq,
                                float inv_count) {
    __shared__ float Xt[16][132];
    __shared__ float Ws[16][128];
    __shared__ float mu_s[FIN], is_s[FIN];
    __shared__ float red_s[128][17], red_d[128][17];
    const float* X = Xp ? Xp : g_x;
    int t = threadIdx.x;
    int tx = t & 15, ty = t >> 4;
    int r0 = blockIdx.x * 128;

    if (DO_BN) {
        if (t < FIN) {
            float mu = sums[t] * inv_count;
            float var = sumsq[t] * inv_count - mu * mu;
            mu_s[t] = mu;
            is_s[t] = rsqrtf(var + 1e-5f);
        }
        __syncthreads();
    }

    float acc[8][8];
#pragma unroll
    for (int i = 0; i < 8; i++)
#pragma unroll
        for (int j = 0; j < 8; j++) acc[i][j] = 0.f;

    for (int k0 = 0; k0 < FIN; k0 += 16) {
#pragma unroll
        for (int i = 0; i < 8; i++) {
            int lin = t + 256 * i;
            int kk = lin & 15, r = lin >> 4;
            float v = X[(r0 + r) * FIN + k0 + kk];
            if (DO_BN) v = (v - mu_s[k0 + kk]) * is_s[k0 + kk];
            Xt[kk][r] = v;
        }
#pragma unroll
        for (int i = 0; i < 8; i++) {
            int lin = t + 256 * i;
            int c = lin & 127, kk = lin >> 7;
            Ws[kk][c] = W[(k0 + kk) * 128 + c];
        }
        __syncthreads();
#pragma unroll
        for (int kk = 0; kk < 16; kk++) {
            float4 a0 = *reinterpret_cast<const float4*>(&Xt[kk][ty * 8]);
            float4 a1 = *reinterpret_cast<const float4*>(&Xt[kk][ty * 8 + 4]);
            float4 b0 = *reinterpret_cast<const float4*>(&Ws[kk][tx * 8]);
            float4 b1 = *reinterpret_cast<const float4*>(&Ws[kk][tx * 8 + 4]);
            float a[8] = {a0.x, a0.y, a0.z, a0.w, a1.x, a1.y, a1.z, a1.w};
            float b[8] = {b0.x, b0.y, b0.z, b0.w, b1.x, b1.y, b1.z, b1.w};
#pragma unroll
            for (int i = 0; i < 8; i++)
#pragma unroll
                for (int j = 0; j < 8; j++) acc[i][j] += a[i] * b[j];
        }
        __syncthreads();
    }

    float4 asv0 = *reinterpret_cast<const float4*>(&a_s[tx * 8]);
    float4 asv1 = *reinterpret_cast<const float4*>(&a_s[tx * 8 + 4]);
    float4 adv0 = *reinterpret_cast<const float4*>(&a_d[tx * 8]);
    float4 adv1 = *reinterpret_cast<const float4*>(&a_d[tx * 8 + 4]);
    float asr[8] = {asv0.x, asv0.y, asv0.z, asv0.w, asv1.x, asv1.y, asv1.z, asv1.w};
    float adr[8] = {adv0.x, adv0.y, adv0.z, adv0.w, adv1.x, adv1.y, adv1.z, adv1.w};
#pragma unroll
    for (int i = 0; i < 8; i++) {
        int row = ty * 8 + i;
        float4 v0 = make_float4(acc[i][0], acc[i][1], acc[i][2], acc[i][3]);
        float4 v1 = make_float4(acc[i][4], acc[i][5], acc[i][6], acc[i][7]);
        *reinterpret_cast<float4*>(&g_h[(r0 + row) * 128 + tx * 8]) = v0;
        *reinterpret_cast<float4*>(&g_h[(r0 + row) * 128 + tx * 8 + 4]) = v1;
        float ps = 0.f, pd = 0.f;
#pragma unroll
        for (int j = 0; j < 8; j++) { ps += acc[i][j] * asr[j]; pd += acc[i][j] * adr[j]; }
        red_s[row][tx] = ps;
        red_d[row][tx] = pd;
    }
    __syncthreads();
    if (t < 128) {
        float s = 0.f, d = 0.f;
#pragma unroll
        for (int k = 0; k < 16; k++) { s += red_s[t][k]; d += red_d[t][k]; }
        g_es[r0 + t] = s;
        g_ed[r0 + t] = d;
    }
}

// ---------------- fused aggregate + pool + bias + relu + BN stats ----------------
// 512 threads, 16 warps; warp per dst node; smem-staged (src, weight); warp pairs pool.
__global__ void aggregate_pool_kernel(int cbase, const float* __restrict__ bias,
                                      float* __restrict__ sums, float* __restrict__ sumsq) {
    __shared__ int sh_s[16][CAP];
    __shared__ float sh_w[16][CAP];
    __shared__ float4 buf[8][32];
    __shared__ float ssum[128], ssq[128];
    int t = threadIdx.x;
    int wp = t >> 5;          // 0..15
    int lane = t & 31;
    if (t < 128) { ssum[t] = 0.f; ssq[t] = 0.f; }
    int w = blockIdx.x * 16 + wp;

    int n = min(g_cnt[cbase + w], CAP);
    int base = (cbase + w) * CAP;
    float ed_d = g_ed[w];
    float selflog = lrelu(g_es[w] + ed_d);

    // stage (src, logit), running max
    float mx = selflog;
    for (int i = lane; i < n; i += 32) {
        int s = g_adj[base + i];
        float lg = lrelu(g_es[s] + ed_d);
        sh_s[wp][i] = s;
        sh_w[wp][i] = lg;
        mx = fmaxf(mx, lg);
    }
#pragma unroll
    for (int o = 16; o; o >>= 1) mx = fmaxf(mx, __shfl_xor_sync(0xffffffffu, mx, o));
    __syncwarp();
    // exponentiate in place
    for (int i = lane; i < n; i += 32)
        sh_w[wp][i] = __expf(sh_w[wp][i] - mx);
    __syncwarp();

    const float4* h4 = reinterpret_cast<const float4*>(g_h);
    float ws = __expf(selflog - mx);
    float4 hd = h4[w * 32 + lane];
    float4 acc = make_float4(ws * hd.x, ws * hd.y, ws * hd.z, ws * hd.w);
    float den = ws;   // lane-uniform
#pragma unroll 8
    for (int j = 0; j < n; j++) {
        int s = sh_s[wp][j];
        float wt = sh_w[wp][j];
        den += wt;
        float4 hv = h4[s * 32 + lane];
        acc.x += wt * hv.x; acc.y += wt * hv.y; acc.z += wt * hv.z; acc.w += wt * hv.w;
    }
    float inv = 1.f / den;
    acc.x *= inv; acc.y *= inv; acc.z *= inv; acc.w *= inv;

    // pool pairs (even warp deposits, odd warp combines)
    if (!(wp & 1)) buf[wp >> 1][lane] = acc;
    __syncthreads();
    if (wp & 1) {
        float4 a = buf[wp >> 1][lane];
        float4 bv = reinterpret_cast<const float4*>(bias)[lane];
        float4 v;
        v.x = fmaxf(fmaxf(a.x, acc.x) + bv.x, 0.f);
        v.y = fmaxf(fmaxf(a.y, acc.y) + bv.y, 0.f);
        v.z = fmaxf(fmaxf(a.z, acc.z) + bv.z, 0.f);
        v.w = fmaxf(fmaxf(a.w, acc.w) + bv.w, 0.f);
        int j = blockIdx.x * 8 + (wp >> 1);
        reinterpret_cast<float4*>(g_x)[j * 32 + lane] = v;
        int c = lane * 4;
        atomicAdd(&ssum[c], v.x);     atomicAdd(&ssq[c], v.x * v.x);
        atomicAdd(&ssum[c + 1], v.y); atomicAdd(&ssq[c + 1], v.y * v.y);
        atomicAdd(&ssum[c + 2], v.z); atomicAdd(&ssq[c + 2], v.z * v.z);
        atomicAdd(&ssum[c + 3], v.w); atomicAdd(&ssq[c + 3], v.w * v.w);
    }
    __syncthreads();
    if (t < 128) {
        atomicAdd(&sums[t], ssum[t]);
        atomicAdd(&sumsq[t], ssq[t]);
    }
}

__global__ void bn_apply_kernel(int Mout, float* __restrict__ outp,
                                const float* __restrict__ sums, const float* __restrict__ sumsq) {
    int idx = blockIdx.x * blockDim.x + threadIdx.x;
    if (idx >= Mout * 128) return;
    int c = idx & 127;
    float inv = 1.f / (float)Mout;
    float mu = sums[c] * inv;
    float var = sumsq[c] * inv - mu * mu;
    outp[idx] = (g_x[idx] - mu) * rsqrtf(var + 1e-5f);
}

// ---------------- launch ----------------
extern "C" void kernel_launch(void* const* d_in, const int* in_sizes, int n_in,
                              void* d_out, int out_size) {
    const float* x    = (const float*)d_in[0];
    const float* W0   = (const float*)d_in[1];
    const float* W1   = (const float*)d_in[2];
    const float* W2   = (const float*)d_in[3];
    const float* as_  = (const float*)d_in[4];
    const float* ad_  = (const float*)d_in[5];
    const float* bias = (const float*)d_in[6];
    const int*   ei   = (const int*)d_in[7];
    float* out = (float*)d_out;

    float* sum_p; float* ssq_p;
    cudaGetSymbolAddress((void**)&sum_p, g_sum);
    cudaGetSymbolAddress((void**)&ssq_p, g_sumsq);

    clear_kernel<<<(BM_TOT + 255) / 256, 256>>>();
    build_csr_kernel<<<E0 / 256, 256>>>(ei);

    // layer 0
    gemm_att_kernel<64, false><<<M0 / 128, 256>>>(x, W0, as_, ad_, nullptr, nullptr, 0.f);
    aggregate_pool_kernel<<<M0 / 16, 512>>>(0, bias, sum_p, ssq_p);

    // layer 1
    gemm_att_kernel<128, true><<<16384 / 128, 256>>>(nullptr, W1, as_ + 128, ad_ + 128,
                                                     sum_p, ssq_p, 1.f / 16384.f);
    aggregate_pool_kernel<<<16384 / 16, 512>>>(M0, bias + 128, sum_p + 128, ssq_p + 128);

    // layer 2
    gemm_att_kernel<128, true><<<8192 / 128, 256>>>(nullptr, W2, as_ + 256, ad_ + 256,
                                                    sum_p + 128, ssq_p + 128, 1.f / 8192.f);
    aggregate_pool_kernel<<<8192 / 16, 512>>>(M0 + M0 / 2, bias + 256, sum_p + 256, ssq_p + 256);

    // final BN -> output
    bn_apply_kernel<<<(4096 * 128) / 256, 256>>>(4096, out, sum_p + 256, ssq_p + 256);
}

// round 6
// speedup vs baseline: 2.2722x; 1.0165x over previous
#include <cuda_runtime.h>
#include <math.h>

static constexpr int M0 = 32768;     // B*N nodes at layer 0
static constexpr int E0 = 262144;    // edges
static constexpr int CAP = 96;       // bucket capacity (max in-degree ~55 at layer 2)
static constexpr int CNT_TOT = M0 + M0 / 2 + M0 / 4;           // 57344
static constexpr int BM0_WORDS = (16384 * 512) / 32;           // 262144
static constexpr int BM1_WORDS = (8192 * 256) / 32;            // 65536
static constexpr int BM_TOT = BM0_WORDS + BM1_WORDS;           // 327680

// ---------------- device scratch ----------------
__device__ float g_h[M0 * 128];
__device__ float g_x[(M0 / 2) * 128];
__device__ float g_es[M0];
__device__ float g_ed[M0];
__device__ int g_adj[CNT_TOT * CAP];
__device__ int g_cnt[CNT_TOT];
__device__ unsigned g_bitmap[BM_TOT];
__device__ float g_sum[3][128];
__device__ float g_sumsq[3][128];

__device__ __forceinline__ float lrelu(float x) { return x > 0.f ? x : 0.2f * x; }

// ---------------- setup ----------------

__global__ void clear_kernel() {
    int i = blockIdx.x * blockDim.x + threadIdx.x;
    if (i < BM_TOT) g_bitmap[i] = 0u;
    if (i < CNT_TOT) g_cnt[i] = 0;
    if (i < 3 * 128) { (&g_sum[0][0])[i] = 0.f; (&g_sumsq[0][0])[i] = 0.f; }
}

// build adjacency buckets for all three layers in one pass (dedupe commutes with pooling)
__global__ void build_csr_kernel(const int* __restrict__ ei) {
    int e = blockIdx.x * blockDim.x + threadIdx.x;
    if (e >= E0) return;
    int s0 = ei[e];
    int d0 = ei[E0 + e];
    if (s0 == d0) return;
    int p = atomicAdd(&g_cnt[d0], 1);
    if (p < CAP) g_adj[d0 * CAP + p] = s0;
    int s1 = s0 >> 1, d1 = d0 >> 1;
    if (s1 == d1) return;
    unsigned key1 = (unsigned)s1 * 512u + (unsigned)(d1 & 511);
    unsigned bit1 = 1u << (key1 & 31);
    if (!(atomicOr(&g_bitmap[key1 >> 5], bit1) & bit1)) {
        p = atomicAdd(&g_cnt[M0 + d1], 1);
        if (p < CAP) g_adj[(M0 + d1) * CAP + p] = s1;
    }
    int s2 = s1 >> 1, d2 = d1 >> 1;
    if (s2 == d2) return;
    unsigned key2 = (unsigned)s2 * 256u + (unsigned)(d2 & 255);
    unsigned bit2 = 1u << (key2 & 31);
    if (!(atomicOr(&g_bitmap[BM0_WORDS + (key2 >> 5)], bit2) & bit2)) {
        p = atomicAdd(&g_cnt[M0 + M0 / 2 + d2], 1);
        if (p < CAP) g_adj[(M0 + M0 / 2 + d2) * CAP + p] = s2;
    }
}

// ---------------- fused GEMM (+BN-on-load, +attention epilogue) ----------------
template <int FIN, bool DO_BN>
__global__ void gemm_att_kernel(const float* __restrict__ Xp, const float* __restrict__ W,
                                const float* __restrict__ a_s, const float* __restrict__ a_d,
                                const float* __restrict__ sums, const float* __restrict__ sumsq,
                                float inv_count) {
    __shared__ float Xt[16][132];
    __shared__ float Ws[16][128];
    __shared__ float mu_s[FIN], is_s[FIN];
    __shared__ float red_s[128][17], red_d[128][17];
    const float* X = Xp ? Xp : g_x;
    int t = threadIdx.x;
    int tx = t & 15, ty = t >> 4;
    int r0 = blockIdx.x * 128;

    if (DO_BN) {
        if (t < FIN) {
            float mu = sums[t] * inv_count;
            float var = sumsq[t] * inv_count - mu * mu;
            mu_s[t] = mu;
            is_s[t] = rsqrtf(var + 1e-5f);
        }
        __syncthreads();
    }

    float acc[8][8];
#pragma unroll
    for (int i = 0; i < 8; i++)
#pragma unroll
        for (int j = 0; j < 8; j++) acc[i][j] = 0.f;

    for (int k0 = 0; k0 < FIN; k0 += 16) {
#pragma unroll
        for (int i = 0; i < 8; i++) {
            int lin = t + 256 * i;
            int kk = lin & 15, r = lin >> 4;
            float v = X[(r0 + r) * FIN + k0 + kk];
            if (DO_BN) v = (v - mu_s[k0 + kk]) * is_s[k0 + kk];
            Xt[kk][r] = v;
        }
#pragma unroll
        for (int i = 0; i < 8; i++) {
            int lin = t + 256 * i;
            int c = lin & 127, kk = lin >> 7;
            Ws[kk][c] = W[(k0 + kk) * 128 + c];
        }
        __syncthreads();
#pragma unroll
        for (int kk = 0; kk < 16; kk++) {
            float4 a0 = *reinterpret_cast<const float4*>(&Xt[kk][ty * 8]);
            float4 a1 = *reinterpret_cast<const float4*>(&Xt[kk][ty * 8 + 4]);
            float4 b0 = *reinterpret_cast<const float4*>(&Ws[kk][tx * 8]);
            float4 b1 = *reinterpret_cast<const float4*>(&Ws[kk][tx * 8 + 4]);
            float a[8] = {a0.x, a0.y, a0.z, a0.w, a1.x, a1.y, a1.z, a1.w};
            float b[8] = {b0.x, b0.y, b0.z, b0.w, b1.x, b1.y, b1.z, b1.w};
#pragma unroll
            for (int i = 0; i < 8; i++)
#pragma unroll
                for (int j = 0; j < 8; j++) acc[i][j] += a[i] * b[j];
        }
        __syncthreads();
    }

    float4 asv0 = *reinterpret_cast<const float4*>(&a_s[tx * 8]);
    float4 asv1 = *reinterpret_cast<const float4*>(&a_s[tx * 8 + 4]);
    float4 adv0 = *reinterpret_cast<const float4*>(&a_d[tx * 8]);
    float4 adv1 = *reinterpret_cast<const float4*>(&a_d[tx * 8 + 4]);
    float asr[8] = {asv0.x, asv0.y, asv0.z, asv0.w, asv1.x, asv1.y, asv1.z, asv1.w};
    float adr[8] = {adv0.x, adv0.y, adv0.z, adv0.w, adv1.x, adv1.y, adv1.z, adv1.w};
#pragma unroll
    for (int i = 0; i < 8; i++) {
        int row = ty * 8 + i;
        float4 v0 = make_float4(acc[i][0], acc[i][1], acc[i][2], acc[i][3]);
        float4 v1 = make_float4(acc[i][4], acc[i][5], acc[i][6], acc[i][7]);
        *reinterpret_cast<float4*>(&g_h[(r0 + row) * 128 + tx * 8]) = v0;
        *reinterpret_cast<float4*>(&g_h[(r0 + row) * 128 + tx * 8 + 4]) = v1;
        float ps = 0.f, pd = 0.f;
#pragma unroll
        for (int j = 0; j < 8; j++) { ps += acc[i][j] * asr[j]; pd += acc[i][j] * adr[j]; }
        red_s[row][tx] = ps;
        red_d[row][tx] = pd;
    }
    __syncthreads();
    if (t < 128) {
        float s = 0.f, d = 0.f;
#pragma unroll
        for (int k = 0; k < 16; k++) { s += red_s[t][k]; d += red_d[t][k]; }
        g_es[r0 + t] = s;
        g_ed[r0 + t] = d;
    }
}

// ---------------- fused aggregate + pool + bias + relu + BN stats ----------------
// 512 threads, 16 warps; warp per dst node; register-staged logits, dual accumulators.
__global__ void __launch_bounds__(512) aggregate_pool_kernel(
        int cbase, const float* __restrict__ bias,
        float* __restrict__ sums, float* __restrict__ sumsq) {
    __shared__ int sh_s[16][CAP];
    __shared__ float sh_w[16][CAP];
    __shared__ float4 buf[8][32];
    __shared__ float ssum[128], ssq[128];
    int t = threadIdx.x;
    int wp = t >> 5;          // 0..15
    int lane = t & 31;
    if (t < 128) { ssum[t] = 0.f; ssq[t] = 0.f; }
    int w = blockIdx.x * 16 + wp;

    int n = min(g_cnt[cbase + w], CAP);
    int base = (cbase + w) * CAP;
    float ed_d = g_ed[w];
    float selflog = lrelu(g_es[w] + ed_d);

    // register-staged (src, logit) for up to 3 chunks of 32 (CAP=96)
    int sreg[3];
    float lreg[3];
    float mx = selflog;
#pragma unroll
    for (int c = 0; c < 3; c++) {
        int i = c * 32 + lane;
        sreg[c] = 0; lreg[c] = -1e30f;
        if (i < n) {
            int s = g_adj[base + i];
            sreg[c] = s;
            lreg[c] = lrelu(g_es[s] + ed_d);
            mx = fmaxf(mx, lreg[c]);
        }
    }
#pragma unroll
    for (int o = 16; o; o >>= 1) mx = fmaxf(mx, __shfl_xor_sync(0xffffffffu, mx, o));
    // one-pass store: src + exp weight
#pragma unroll
    for (int c = 0; c < 3; c++) {
        int i = c * 32 + lane;
        if (i < n) {
            sh_s[wp][i] = sreg[c];
            sh_w[wp][i] = __expf(lreg[c] - mx);
        }
    }
    __syncwarp();

    const float4* h4 = reinterpret_cast<const float4*>(g_h);
    float ws = __expf(selflog - mx);
    float4 hd = h4[w * 32 + lane];
    float4 acc0 = make_float4(ws * hd.x, ws * hd.y, ws * hd.z, ws * hd.w);
    float4 acc1 = make_float4(0.f, 0.f, 0.f, 0.f);
    float den0 = ws, den1 = 0.f;     // lane-uniform
    int j = 0;
#pragma unroll 4
    for (; j + 1 < n; j += 2) {
        int sA = sh_s[wp][j], sB = sh_s[wp][j + 1];
        float wA = sh_w[wp][j], wB = sh_w[wp][j + 1];
        float4 hA = h4[sA * 32 + lane];
        float4 hB = h4[sB * 32 + lane];
        den0 += wA; den1 += wB;
        acc0.x += wA * hA.x; acc0.y += wA * hA.y; acc0.z += wA * hA.z; acc0.w += wA * hA.w;
        acc1.x += wB * hB.x; acc1.y += wB * hB.y; acc1.z += wB * hB.z; acc1.w += wB * hB.w;
    }
    if (j < n) {
        int sA = sh_s[wp][j];
        float wA = sh_w[wp][j];
        float4 hA = h4[sA * 32 + lane];
        den0 += wA;
        acc0.x += wA * hA.x; acc0.y += wA * hA.y; acc0.z += wA * hA.z; acc0.w += wA * hA.w;
    }
    float inv = 1.f / (den0 + den1);
    float4 acc = make_float4((acc0.x + acc1.x) * inv, (acc0.y + acc1.y) * inv,
                             (acc0.z + acc1.z) * inv, (acc0.w + acc1.w) * inv);

    // pool pairs (even warp deposits, odd warp combines)
    if (!(wp & 1)) buf[wp >> 1][lane] = acc;
    __syncthreads();
    if (wp & 1) {
        float4 a = buf[wp >> 1][lane];
        float4 bv = reinterpret_cast<const float4*>(bias)[lane];
        float4 v;
        v.x = fmaxf(fmaxf(a.x, acc.x) + bv.x, 0.f);
        v.y = fmaxf(fmaxf(a.y, acc.y) + bv.y, 0.f);
        v.z = fmaxf(fmaxf(a.z, acc.z) + bv.z, 0.f);
        v.w = fmaxf(fmaxf(a.w, acc.w) + bv.w, 0.f);
        int jj = blockIdx.x * 8 + (wp >> 1);
        reinterpret_cast<float4*>(g_x)[jj * 32 + lane] = v;
        int c = lane * 4;
        atomicAdd(&ssum[c], v.x);     atomicAdd(&ssq[c], v.x * v.x);
        atomicAdd(&ssum[c + 1], v.y); atomicAdd(&ssq[c + 1], v.y * v.y);
        atomicAdd(&ssum[c + 2], v.z); atomicAdd(&ssq[c + 2], v.z * v.z);
        atomicAdd(&ssum[c + 3], v.w); atomicAdd(&ssq[c + 3], v.w * v.w);
    }
    __syncthreads();
    if (t < 128) {
        atomicAdd(&sums[t], ssum[t]);
        atomicAdd(&sumsq[t], ssq[t]);
    }
}

__global__ void bn_apply_kernel(int Mout, float* __restrict__ outp,
                                const float* __restrict__ sums, const float* __restrict__ sumsq) {
    int idx = blockIdx.x * blockDim.x + threadIdx.x;
    if (idx >= Mout * 128) return;
    int c = idx & 127;
    float inv = 1.f / (float)Mout;
    float mu = sums[c] * inv;
    float var = sumsq[c] * inv - mu * mu;
    outp[idx] = (g_x[idx] - mu) * rsqrtf(var + 1e-5f);
}

// ---------------- launch ----------------
extern "C" void kernel_launch(void* const* d_in, const int* in_sizes, int n_in,
                              void* d_out, int out_size) {
    const float* x    = (const float*)d_in[0];
    const float* W0   = (const float*)d_in[1];
    const float* W1   = (const float*)d_in[2];
    const float* W2   = (const float*)d_in[3];
    const float* as_  = (const float*)d_in[4];
    const float* ad_  = (const float*)d_in[5];
    const float* bias = (const float*)d_in[6];
    const int*   ei   = (const int*)d_in[7];
    float* out = (float*)d_out;

    float* sum_p; float* ssq_p;
    cudaGetSymbolAddress((void**)&sum_p, g_sum);
    cudaGetSymbolAddress((void**)&ssq_p, g_sumsq);

    // one-time infra (host-side objects only; same launches every call)
    static cudaStream_t side = nullptr;
    static cudaEvent_t e0 = nullptr, e1 = nullptr;
    if (!side) {
        cudaStreamCreateWithFlags(&side, cudaStreamNonBlocking);
        cudaEventCreateWithFlags(&e0, cudaEventDisableTiming);
        cudaEventCreateWithFlags(&e1, cudaEventDisableTiming);
    }

    // fork: CSR build on side stream, concurrent with layer-0 GEMM
    cudaEventRecord(e0, 0);
    cudaStreamWaitEvent(side, e0, 0);
    clear_kernel<<<(BM_TOT + 255) / 256, 256, 0, side>>>();
    build_csr_kernel<<<E0 / 256, 256, 0, side>>>(ei);
    cudaEventRecord(e1, side);

    // layer 0 GEMM (independent of adjacency)
    gemm_att_kernel<64, false><<<M0 / 128, 256>>>(x, W0, as_, ad_, nullptr, nullptr, 0.f);

    // join before aggregation
    cudaStreamWaitEvent(0, e1, 0);
    aggregate_pool_kernel<<<M0 / 16, 512>>>(0, bias, sum_p, ssq_p);

    // layer 1
    gemm_att_kernel<128, true><<<16384 / 128, 256>>>(nullptr, W1, as_ + 128, ad_ + 128,
                                                     sum_p, ssq_p, 1.f / 16384.f);
    aggregate_pool_kernel<<<16384 / 16, 512>>>(M0, bias + 128, sum_p + 128, ssq_p + 128);

    // layer 2
    gemm_att_kernel<128, true><<<8192 / 128, 256>>>(nullptr, W2, as_ + 256, ad_ + 256,
                                                    sum_p + 128, ssq_p + 128, 1.f / 8192.f);
    aggregate_pool_kernel<<<8192 / 16, 512>>>(M0 + M0 / 2, bias + 256, sum_p + 256, ssq_p + 256);

    // final BN -> output
    bn_apply_kernel<<<(4096 * 128) / 256, 256>>>(4096, out, sum_p + 256, ssq_p + 256);
}

// round 7
// speedup vs baseline: 2.3624x; 1.0397x over previous
#include <cuda_runtime.h>
#include <math.h>

static constexpr int M0 = 32768;     // B*N nodes at layer 0
static constexpr int E0 = 262144;    // edges
static constexpr int CAP = 96;       // bucket capacity (max in-degree ~55 at layer 2)
static constexpr int CNT_TOT = M0 + M0 / 2 + M0 / 4;           // 57344
static constexpr int BM0_WORDS = (16384 * 512) / 32;           // 262144
static constexpr int BM1_WORDS = (8192 * 256) / 32;            // 65536
static constexpr int BM_TOT = BM0_WORDS + BM1_WORDS;           // 327680

// ---------------- device scratch ----------------
__device__ float g_h[M0 * 128];
__device__ float g_x[(M0 / 2) * 128];
__device__ float g_es[M0];
__device__ float g_ed[M0];
__device__ int g_adj[CNT_TOT * CAP];
__device__ int g_cnt[CNT_TOT];
__device__ unsigned g_bitmap[BM_TOT];
__device__ float g_sum[3][128];
__device__ float g_sumsq[3][128];

__device__ __forceinline__ float lrelu(float x) { return x > 0.f ? x : 0.2f * x; }

// ---------------- setup ----------------

__global__ void clear_kernel() {
    int i = blockIdx.x * blockDim.x + threadIdx.x;
    if (i < BM_TOT) g_bitmap[i] = 0u;
    if (i < CNT_TOT) g_cnt[i] = 0;
    if (i < 3 * 128) { (&g_sum[0][0])[i] = 0.f; (&g_sumsq[0][0])[i] = 0.f; }
}

// build adjacency buckets for all three layers in one pass (dedupe commutes with pooling)
__global__ void build_csr_kernel(const int* __restrict__ ei) {
    int e = blockIdx.x * blockDim.x + threadIdx.x;
    if (e >= E0) return;
    int s0 = ei[e];
    int d0 = ei[E0 + e];
    if (s0 == d0) return;
    int p = atomicAdd(&g_cnt[d0], 1);
    if (p < CAP) g_adj[d0 * CAP + p] = s0;
    int s1 = s0 >> 1, d1 = d0 >> 1;
    if (s1 == d1) return;
    unsigned key1 = (unsigned)s1 * 512u + (unsigned)(d1 & 511);
    unsigned bit1 = 1u << (key1 & 31);
    if (!(atomicOr(&g_bitmap[key1 >> 5], bit1) & bit1)) {
        p = atomicAdd(&g_cnt[M0 + d1], 1);
        if (p < CAP) g_adj[(M0 + d1) * CAP + p] = s1;
    }
    int s2 = s1 >> 1, d2 = d1 >> 1;
    if (s2 == d2) return;
    unsigned key2 = (unsigned)s2 * 256u + (unsigned)(d2 & 255);
    unsigned bit2 = 1u << (key2 & 31);
    if (!(atomicOr(&g_bitmap[BM0_WORDS + (key2 >> 5)], bit2) & bit2)) {
        p = atomicAdd(&g_cnt[M0 + M0 / 2 + d2], 1);
        if (p < CAP) g_adj[(M0 + M0 / 2 + d2) * CAP + p] = s2;
    }
}

// ---------------- fused GEMM (+BN-on-load, +attention epilogue) ----------------
template <int FIN, bool DO_BN>
__global__ void gemm_att_kernel(const float* __restrict__ Xp, const float* __restrict__ W,
                                const float* __restrict__ a_s, const float* __restrict__ a_d,
                                const float* __restrict__ sums, const float* __restrict__ sumsq,
                                float inv_count) {
    __shared__ float Xt[16][132];
    __shared__ float Ws[16][128];
    __shared__ float mu_s[FIN], is_s[FIN];
    __shared__ float red_s[128][17], red_d[128][17];
    const float* X = Xp ? Xp : g_x;
    int t = threadIdx.x;
    int tx = t & 15, ty = t >> 4;
    int r0 = blockIdx.x * 128;

    if (DO_BN) {
        if (t < FIN) {
            float mu = sums[t] * inv_count;
            float var = sumsq[t] * inv_count - mu * mu;
            mu_s[t] = mu;
            is_s[t] = rsqrtf(var + 1e-5f);
        }
        __syncthreads();
    }

    float acc[8][8];
#pragma unroll
    for (int i = 0; i < 8; i++)
#pragma unroll
        for (int j = 0; j < 8; j++) acc[i][j] = 0.f;

    for (int k0 = 0; k0 < FIN; k0 += 16) {
#pragma unroll
        for (int i = 0; i < 8; i++) {
            int lin = t + 256 * i;
            int kk = lin & 15, r = lin >> 4;
            float v = X[(r0 + r) * FIN + k0 + kk];
            if (DO_BN) v = (v - mu_s[k0 + kk]) * is_s[k0 + kk];
            Xt[kk][r] = v;
        }
#pragma unroll
        for (int i = 0; i < 8; i++) {
            int lin = t + 256 * i;
            int c = lin & 127, kk = lin >> 7;
            Ws[kk][c] = W[(k0 + kk) * 128 + c];
        }
        __syncthreads();
#pragma unroll
        for (int kk = 0; kk < 16; kk++) {
            float4 a0 = *reinterpret_cast<const float4*>(&Xt[kk][ty * 8]);
            float4 a1 = *reinterpret_cast<const float4*>(&Xt[kk][ty * 8 + 4]);
            float4 b0 = *reinterpret_cast<const float4*>(&Ws[kk][tx * 8]);
            float4 b1 = *reinterpret_cast<const float4*>(&Ws[kk][tx * 8 + 4]);
            float a[8] = {a0.x, a0.y, a0.z, a0.w, a1.x, a1.y, a1.z, a1.w};
            float b[8] = {b0.x, b0.y, b0.z, b0.w, b1.x, b1.y, b1.z, b1.w};
#pragma unroll
            for (int i = 0; i < 8; i++)
#pragma unroll
                for (int j = 0; j < 8; j++) acc[i][j] += a[i] * b[j];
        }
        __syncthreads();
    }

    float4 asv0 = *reinterpret_cast<const float4*>(&a_s[tx * 8]);
    float4 asv1 = *reinterpret_cast<const float4*>(&a_s[tx * 8 + 4]);
    float4 adv0 = *reinterpret_cast<const float4*>(&a_d[tx * 8]);
    float4 adv1 = *reinterpret_cast<const float4*>(&a_d[tx * 8 + 4]);
    float asr[8] = {asv0.x, asv0.y, asv0.z, asv0.w, asv1.x, asv1.y, asv1.z, asv1.w};
    float adr[8] = {adv0.x, adv0.y, adv0.z, adv0.w, adv1.x, adv1.y, adv1.z, adv1.w};
#pragma unroll
    for (int i = 0; i < 8; i++) {
        int row = ty * 8 + i;
        float4 v0 = make_float4(acc[i][0], acc[i][1], acc[i][2], acc[i][3]);
        float4 v1 = make_float4(acc[i][4], acc[i][5], acc[i][6], acc[i][7]);
        *reinterpret_cast<float4*>(&g_h[(r0 + row) * 128 + tx * 8]) = v0;
        *reinterpret_cast<float4*>(&g_h[(r0 + row) * 128 + tx * 8 + 4]) = v1;
        float ps = 0.f, pd = 0.f;
#pragma unroll
        for (int j = 0; j < 8; j++) { ps += acc[i][j] * asr[j]; pd += acc[i][j] * adr[j]; }
        red_s[row][tx] = ps;
        red_d[row][tx] = pd;
    }
    __syncthreads();
    if (t < 128) {
        float s = 0.f, d = 0.f;
#pragma unroll
        for (int k = 0; k < 16; k++) { s += red_s[t][k]; d += red_d[t][k]; }
        g_es[r0 + t] = s;
        g_ed[r0 + t] = d;
    }
}

// ---------------- fused aggregate + pool + bias + relu + BN stats ----------------
// 256 threads, 8 warps; each warp owns one POOL PAIR (nodes 2j, 2j+1):
// two independent softmax-gather chains interleaved (2x MLP), pooled in registers.
__global__ void __launch_bounds__(256) aggregate_pool_kernel(
        int cbase, const float* __restrict__ bias,
        float* __restrict__ sums, float* __restrict__ sumsq) {
    __shared__ int sh_s[8][2 * CAP];
    __shared__ float sh_w[8][2 * CAP];
    __shared__ float ssum[128], ssq[128];
    int t = threadIdx.x;
    int wp = t >> 5;          // 0..7
    int lane = t & 31;
    if (t < 128) { ssum[t] = 0.f; ssq[t] = 0.f; }
    int j = blockIdx.x * 8 + wp;      // pool-pair index
    int a = 2 * j, b = a + 1;

    int na = min(g_cnt[cbase + a], CAP);
    int nb = min(g_cnt[cbase + b], CAP);
    int base_a = (cbase + a) * CAP;
    int base_b = (cbase + b) * CAP;
    float ed_a = g_ed[a], ed_b = g_ed[b];
    float sl_a = lrelu(g_es[a] + ed_a);
    float sl_b = lrelu(g_es[b] + ed_b);

    // stage (src, logit) for both nodes; track both maxes
    float mxa = sl_a, mxb = sl_b;
    for (int i = lane; i < na; i += 32) {
        int s = g_adj[base_a + i];
        float lg = lrelu(g_es[s] + ed_a);
        sh_s[wp][i] = s;
        sh_w[wp][i] = lg;
        mxa = fmaxf(mxa, lg);
    }
    for (int i = lane; i < nb; i += 32) {
        int s = g_adj[base_b + i];
        float lg = lrelu(g_es[s] + ed_b);
        sh_s[wp][CAP + i] = s;
        sh_w[wp][CAP + i] = lg;
        mxb = fmaxf(mxb, lg);
    }
#pragma unroll
    for (int o = 16; o; o >>= 1) {
        mxa = fmaxf(mxa, __shfl_xor_sync(0xffffffffu, mxa, o));
        mxb = fmaxf(mxb, __shfl_xor_sync(0xffffffffu, mxb, o));
    }
    __syncwarp();
    for (int i = lane; i < na; i += 32) sh_w[wp][i] = __expf(sh_w[wp][i] - mxa);
    for (int i = lane; i < nb; i += 32) sh_w[wp][CAP + i] = __expf(sh_w[wp][CAP + i] - mxb);
    __syncwarp();

    const float4* h4 = reinterpret_cast<const float4*>(g_h);
    float wsa = __expf(sl_a - mxa);
    float wsb = __expf(sl_b - mxb);
    float4 ha = h4[a * 32 + lane];
    float4 hb = h4[b * 32 + lane];
    float4 accA = make_float4(wsa * ha.x, wsa * ha.y, wsa * ha.z, wsa * ha.w);
    float4 accB = make_float4(wsb * hb.x, wsb * hb.y, wsb * hb.z, wsb * hb.w);
    float denA = wsa, denB = wsb;     // lane-uniform
    int nm = max(na, nb);
#pragma unroll 2
    for (int k = 0; k < nm; k++) {
        if (k < na) {
            int s = sh_s[wp][k];
            float wt = sh_w[wp][k];
            float4 hv = h4[s * 32 + lane];
            denA += wt;
            accA.x += wt * hv.x; accA.y += wt * hv.y; accA.z += wt * hv.z; accA.w += wt * hv.w;
        }
        if (k < nb) {
            int s = sh_s[wp][CAP + k];
            float wt = sh_w[wp][CAP + k];
            float4 hv = h4[s * 32 + lane];
            denB += wt;
            accB.x += wt * hv.x; accB.y += wt * hv.y; accB.z += wt * hv.z; accB.w += wt * hv.w;
        }
    }
    float iA = 1.f / denA, iB = 1.f / denB;
    float4 bv = reinterpret_cast<const float4*>(bias)[lane];
    float4 v;
    v.x = fmaxf(fmaxf(accA.x * iA, accB.x * iB) + bv.x, 0.f);
    v.y = fmaxf(fmaxf(accA.y * iA, accB.y * iB) + bv.y, 0.f);
    v.z = fmaxf(fmaxf(accA.z * iA, accB.z * iB) + bv.z, 0.f);
    v.w = fmaxf(fmaxf(accA.w * iA, accB.w * iB) + bv.w, 0.f);
    reinterpret_cast<float4*>(g_x)[j * 32 + lane] = v;

    int c = lane * 4;
    atomicAdd(&ssum[c], v.x);     atomicAdd(&ssq[c], v.x * v.x);
    atomicAdd(&ssum[c + 1], v.y); atomicAdd(&ssq[c + 1], v.y * v.y);
    atomicAdd(&ssum[c + 2], v.z); atomicAdd(&ssq[c + 2], v.z * v.z);
    atomicAdd(&ssum[c + 3], v.w); atomicAdd(&ssq[c + 3], v.w * v.w);
    __syncthreads();
    if (t < 128) {
        atomicAdd(&sums[t], ssum[t]);
        atomicAdd(&sumsq[t], ssq[t]);
    }
}

__global__ void bn_apply_kernel(int Mout, float* __restrict__ outp,
                                const float* __restrict__ sums, const float* __restrict__ sumsq) {
    int idx = blockIdx.x * blockDim.x + threadIdx.x;
    if (idx >= Mout * 128) return;
    int c = idx & 127;
    float inv = 1.f / (float)Mout;
    float mu = sums[c] * inv;
    float var = sumsq[c] * inv - mu * mu;
    outp[idx] = (g_x[idx] - mu) * rsqrtf(var + 1e-5f);
}

// ---------------- launch ----------------
extern "C" void kernel_launch(void* const* d_in, const int* in_sizes, int n_in,
                              void* d_out, int out_size) {
    const float* x    = (const float*)d_in[0];
    const float* W0   = (const float*)d_in[1];
    const float* W1   = (const float*)d_in[2];
    const float* W2   = (const float*)d_in[3];
    const float* as_  = (const float*)d_in[4];
    const float* ad_  = (const float*)d_in[5];
    const float* bias = (const float*)d_in[6];
    const int*   ei   = (const int*)d_in[7];
    float* out = (float*)d_out;

    float* sum_p; float* ssq_p;
    cudaGetSymbolAddress((void**)&sum_p, g_sum);
    cudaGetSymbolAddress((void**)&ssq_p, g_sumsq);

    static cudaStream_t side = nullptr;
    static cudaEvent_t e0 = nullptr, e1 = nullptr;
    if (!side) {
        cudaStreamCreateWithFlags(&side, cudaStreamNonBlocking);
        cudaEventCreateWithFlags(&e0, cudaEventDisableTiming);
        cudaEventCreateWithFlags(&e1, cudaEventDisableTiming);
    }

    // fork: CSR build on side stream, concurrent with layer-0 GEMM
    cudaEventRecord(e0, 0);
    cudaStreamWaitEvent(side, e0, 0);
    clear_kernel<<<(BM_TOT + 255) / 256, 256, 0, side>>>();
    build_csr_kernel<<<E0 / 256, 256, 0, side>>>(ei);
    cudaEventRecord(e1, side);

    // layer 0 GEMM (independent of adjacency)
    gemm_att_kernel<64, false><<<M0 / 128, 256>>>(x, W0, as_, ad_, nullptr, nullptr, 0.f);

    // join before aggregation; aggregate produces 16384 pooled rows (pairs of 32768)
    cudaStreamWaitEvent(0, e1, 0);
    aggregate_pool_kernel<<<16384 / 8, 256>>>(0, bias, sum_p, ssq_p);

    // layer 1
    gemm_att_kernel<128, true><<<16384 / 128, 256>>>(nullptr, W1, as_ + 128, ad_ + 128,
                                                     sum_p, ssq_p, 1.f / 16384.f);
    aggregate_pool_kernel<<<8192 / 8, 256>>>(M0, bias + 128, sum_p + 128, ssq_p + 128);

    // layer 2
    gemm_att_kernel<128, true><<<8192 / 128, 256>>>(nullptr, W2, as_ + 256, ad_ + 256,
                                                    sum_p + 128, ssq_p + 128, 1.f / 8192.f);
    aggregate_pool_kernel<<<4096 / 8, 256>>>(M0 + M0 / 2, bias + 256, sum_p + 256, ssq_p + 256);

    // final BN -> output
    bn_apply_kernel<<<(4096 * 128) / 256, 256>>>(4096, out, sum_p + 256, ssq_p + 256);
}

// round 11
// speedup vs baseline: 2.4000x; 1.0159x over previous
#include <cuda_runtime.h>
#include <cuda_bf16.h>
#include <mma.h>
#include <math.h>
#include <stdint.h>

using namespace nvcuda;

static constexpr int M0 = 32768;     // B*N nodes at layer 0
static constexpr int E0 = 262144;    // edges
static constexpr int CAP = 96;       // bucket capacity
static constexpr int CNT_TOT = M0 + M0 / 2 + M0 / 4;
static constexpr int BM0_WORDS = (16384 * 512) / 32;
static constexpr int BM1_WORDS = (8192 * 256) / 32;
static constexpr int BM_TOT = BM0_WORDS + BM1_WORDS;

// ---------------- device scratch ----------------
__device__ float g_h[M0 * 128];
__device__ float g_x[(M0 / 2) * 128];
__device__ float g_es[M0];
__device__ float g_ed[M0];
__device__ int g_adj[CNT_TOT * CAP];
__device__ int g_cnt[CNT_TOT];
__device__ unsigned g_bitmap[BM_TOT];
__device__ float g_sum[3][128];
__device__ float g_sumsq[3][128];

__device__ __forceinline__ float lrelu(float x) { return x > 0.f ? x : 0.2f * x; }

// ---------------- setup ----------------

__global__ void clear_kernel() {
    int i = blockIdx.x * blockDim.x + threadIdx.x;
    if (i < BM_TOT) g_bitmap[i] = 0u;
    if (i < CNT_TOT) g_cnt[i] = 0;
    if (i < 3 * 128) { (&g_sum[0][0])[i] = 0.f; (&g_sumsq[0][0])[i] = 0.f; }
}

__global__ void build_csr_kernel(const int* __restrict__ ei) {
    int e = blockIdx.x * blockDim.x + threadIdx.x;
    if (e >= E0) return;
    int s0 = ei[e];
    int d0 = ei[E0 + e];
    if (s0 == d0) return;
    int p = atomicAdd(&g_cnt[d0], 1);
    if (p < CAP) g_adj[d0 * CAP + p] = s0;
    int s1 = s0 >> 1, d1 = d0 >> 1;
    if (s1 == d1) return;
    unsigned key1 = (unsigned)s1 * 512u + (unsigned)(d1 & 511);
    unsigned bit1 = 1u << (key1 & 31);
    if (!(atomicOr(&g_bitmap[key1 >> 5], bit1) & bit1)) {
        p = atomicAdd(&g_cnt[M0 + d1], 1);
        if (p < CAP) g_adj[(M0 + d1) * CAP + p] = s1;
    }
    int s2 = s1 >> 1, d2 = d1 >> 1;
    if (s2 == d2) return;
    unsigned key2 = (unsigned)s2 * 256u + (unsigned)(d2 & 255);
    unsigned bit2 = 1u << (key2 & 31);
    if (!(atomicOr(&g_bitmap[BM0_WORDS + (key2 >> 5)], bit2) & bit2)) {
        p = atomicAdd(&g_cnt[M0 + M0 / 2 + d2], 1);
        if (p < CAP) g_adj[(M0 + M0 / 2 + d2) * CAP + p] = s2;
    }
}

// ---------------- WMMA bf16x3 GEMM (+BN-on-load, +attention epilogue) ----------------
// D = Xhi*Whi + Xhi*Wlo + Xlo*Whi  (split-precision: ~1.5e-5 rel err, fp32-grade here)
// block: 256 threads / 8 warps; tile 128x128; warp tile 32x64 (2x4 of 16x16 frags).
// dynamic smem: tiles phase  [Xhi 8K | Xlo 8K | Whi 8K | Wlo 8K],
//               epilogue phase reuses as f32 staging 128x132 (67584 B total alloc).
static constexpr int GEMM_SMEM = 128 * 132 * 4;   // 67584

__device__ __forceinline__ void split_pack(float a, float b, uint32_t& hi, uint32_t& lo) {
    __nv_bfloat16 h0 = __float2bfloat16(a), h1 = __float2bfloat16(b);
    __nv_bfloat16 l0 = __float2bfloat16(a - __bfloat162float(h0));
    __nv_bfloat16 l1 = __float2bfloat16(b - __bfloat162float(h1));
    hi = ((uint32_t)*(uint16_t*)&h1 << 16) | *(uint16_t*)&h0;
    lo = ((uint32_t)*(uint16_t*)&l1 << 16) | *(uint16_t*)&l0;
}

template <int FIN, bool DO_BN>
__global__ void __launch_bounds__(256)
tgemm_att_kernel(const float* __restrict__ Xp, const float* __restrict__ W,
                 const float* __restrict__ a_s, const float* __restrict__ a_d,
                 const float* __restrict__ sums, const float* __restrict__ sumsq,
                 float inv_count) {
    extern __shared__ char smem[];
    __shared__ float sAS[128], sAD[128], sMU[128], sIS[128];
    __nv_bfloat16* Xhi = reinterpret_cast<__nv_bfloat16*>(smem);
    __nv_bfloat16* Xlo = Xhi + 128 * 32;
    __nv_bfloat16* Whi = Xlo + 128 * 32;
    __nv_bfloat16* Wlo = Whi + 32 * 128;
    float* stg = reinterpret_cast<float*>(smem);

    int t = threadIdx.x;
    int w = t >> 5;
    int r0 = blockIdx.x * 128;
    const float* X = Xp ? Xp : g_x;

    if (t < 128) {
        sAS[t] = a_s[t];
        sAD[t] = a_d[t];
        if (DO_BN) {
            float mu = sums[t] * inv_count;
            float var = sumsq[t] * inv_count - mu * mu;
            sMU[t] = mu;
            sIS[t] = rsqrtf(var + 1e-5f);
        }
    }
    __syncthreads();

    int wm = w >> 1, wn = w & 1;   // warp tile: rows [wm*32,+32), cols [wn*64,+64)
    wmma::fragment<wmma::accumulator, 16, 16, 16, float> acc[2][4];
#pragma unroll
    for (int mi = 0; mi < 2; mi++)
#pragma unroll
        for (int ni = 0; ni < 4; ni++) wmma::fill_fragment(acc[mi][ni], 0.f);

    for (int k0 = 0; k0 < FIN; k0 += 32) {
        // X tile: 128 rows x 32 cols -> Xhi/Xlo (ld 32)
#pragma unroll
        for (int i = 0; i < 4; i++) {
            int e = t + 256 * i;           // 0..1023
            int row = e >> 3, c4 = e & 7;
            float4 v = *reinterpret_cast<const float4*>(&X[(size_t)(r0 + row) * FIN + k0 + c4 * 4]);
            if (DO_BN) {
                int cb = k0 + c4 * 4;
                v.x = (v.x - sMU[cb]) * sIS[cb];
                v.y = (v.y - sMU[cb + 1]) * sIS[cb + 1];
                v.z = (v.z - sMU[cb + 2]) * sIS[cb + 2];
                v.w = (v.w - sMU[cb + 3]) * sIS[cb + 3];
            }
            uint32_t h01, l01, h23, l23;
            split_pack(v.x, v.y, h01, l01);
            split_pack(v.z, v.w, h23, l23);
            int idx = row * 32 + c4 * 4;
            *reinterpret_cast<uint32_t*>(&Xhi[idx]) = h01;
            *reinterpret_cast<uint32_t*>(&Xhi[idx + 2]) = h23;
            *reinterpret_cast<uint32_t*>(&Xlo[idx]) = l01;
            *reinterpret_cast<uint32_t*>(&Xlo[idx + 2]) = l23;
        }
        // W tile: 32 rows x 128 cols -> Whi/Wlo (ld 128)
#pragma unroll
        for (int i = 0; i < 4; i++) {
            int e = t + 256 * i;           // 0..1023
            int r = e >> 5, c4 = e & 31;
            float4 v = *reinterpret_cast<const float4*>(&W[(size_t)(k0 + r) * 128 + c4 * 4]);
            uint32_t h01, l01, h23, l23;
            split_pack(v.x, v.y, h01, l01);
            split_pack(v.z, v.w, h23, l23);
            int idx = r * 128 + c4 * 4;
            *reinterpret_cast<uint32_t*>(&Whi[idx]) = h01;
            *reinterpret_cast<uint32_t*>(&Whi[idx + 2]) = h23;
            *reinterpret_cast<uint32_t*>(&Wlo[idx]) = l01;
            *reinterpret_cast<uint32_t*>(&Wlo[idx + 2]) = l23;
        }
        __syncthreads();

#pragma unroll
        for (int kk = 0; kk < 32; kk += 16) {
            wmma::fragment<wmma::matrix_a, 16, 16, 16, __nv_bfloat16, wmma::row_major> ahi[2], alo[2];
            wmma::fragment<wmma::matrix_b, 16, 16, 16, __nv_bfloat16, wmma::row_major> bhi[4], blo[4];
#pragma unroll
            for (int mi = 0; mi < 2; mi++) {
                const __nv_bfloat16* pa = Xhi + (wm * 32 + mi * 16) * 32 + kk;
                wmma::load_matrix_sync(ahi[mi], pa, 32);
                wmma::load_matrix_sync(alo[mi], pa + 128 * 32, 32);   // Xlo
            }
#pragma unroll
            for (int ni = 0; ni < 4; ni++) {
                const __nv_bfloat16* pb = Whi + kk * 128 + wn * 64 + ni * 16;
                wmma::load_matrix_sync(bhi[ni], pb, 128);
                wmma::load_matrix_sync(blo[ni], pb + 32 * 128, 128);  // Wlo
            }
#pragma unroll
            for (int mi = 0; mi < 2; mi++)
#pragma unroll
                for (int ni = 0; ni < 4; ni++) {
                    wmma::mma_sync(acc[mi][ni], ahi[mi], bhi[ni], acc[mi][ni]);
                    wmma::mma_sync(acc[mi][ni], ahi[mi], blo[ni], acc[mi][ni]);
                    wmma::mma_sync(acc[mi][ni], alo[mi], bhi[ni], acc[mi][ni]);
                }
        }
        __syncthreads();
    }

    // ---- epilogue: stage f32 rows (ld 132 -> conflict-free col walks) ----
#pragma unroll
    for (int mi = 0; mi < 2; mi++)
#pragma unroll
        for (int ni = 0; ni < 4; ni++)
            wmma::store_matrix_sync(stg + (wm * 32 + mi * 16) * 132 + wn * 64 + ni * 16,
                                    acc[mi][ni], 132, wmma::mem_row_major);
    __syncthreads();

    // es/ed: thread t<128 owns row t (33-float4 stride -> conflict-free)
    if (t < 128) {
        const float4* row4 = reinterpret_cast<const float4*>(stg) + t * 33;
        const float4* as4 = reinterpret_cast<const float4*>(sAS);
        const float4* ad4 = reinterpret_cast<const float4*>(sAD);
        float es = 0.f, ed = 0.f;
#pragma unroll
        for (int c = 0; c < 32; c++) {
            float4 v = row4[c];
            float4 a = as4[c];
            float4 d = ad4[c];
            es += v.x * a.x + v.y * a.y + v.z * a.z + v.w * a.w;
            ed += v.x * d.x + v.y * d.y + v.z * d.z + v.w * d.w;
        }
        g_es[r0 + t] = es;
        g_ed[r0 + t] = ed;
    }
    // coalesced copy staging -> g_h
#pragma unroll
    for (int i = 0; i < 16; i++) {
        int e4 = t + 256 * i;                 // 0..4095
        int row = e4 >> 5, c4 = e4 & 31;
        reinterpret_cast<float4*>(&g_h[(size_t)(r0 + row) * 128])[c4] =
            reinterpret_cast<const float4*>(stg + row * 132)[c4];
    }
}

// ---------------- fused aggregate + pool + bias + relu + BN stats ----------------
__global__ void __launch_bounds__(256) aggregate_pool_kernel(
        int cbase, const float* __restrict__ bias,
        float* __restrict__ sums, float* __restrict__ sumsq) {
    __shared__ int sh_s[8][2 * CAP];
    __shared__ float sh_w[8][2 * CAP];
    __shared__ float ssum[128], ssq[128];
    int t = threadIdx.x;
    int wp = t >> 5;
    int lane = t & 31;
    if (t < 128) { ssum[t] = 0.f; ssq[t] = 0.f; }
    int j = blockIdx.x * 8 + wp;
    int a = 2 * j, b = a + 1;

    int na = min(g_cnt[cbase + a], CAP);
    int nb = min(g_cnt[cbase + b], CAP);
    int base_a = (cbase + a) * CAP;
    int base_b = (cbase + b) * CAP;
    float ed_a = g_ed[a], ed_b = g_ed[b];
    float sl_a = lrelu(g_es[a] + ed_a);
    float sl_b = lrelu(g_es[b] + ed_b);

    float mxa = sl_a, mxb = sl_b;
    for (int i = lane; i < na; i += 32) {
        int s = g_adj[base_a + i];
        float lg = lrelu(g_es[s] + ed_a);
        sh_s[wp][i] = s;
        sh_w[wp][i] = lg;
        mxa = fmaxf(mxa, lg);
    }
    for (int i = lane; i < nb; i += 32) {
        int s = g_adj[base_b + i];
        float lg = lrelu(g_es[s] + ed_b);
        sh_s[wp][CAP + i] = s;
        sh_w[wp][CAP + i] = lg;
        mxb = fmaxf(mxb, lg);
    }
#pragma unroll
    for (int o = 16; o; o >>= 1) {
        mxa = fmaxf(mxa, __shfl_xor_sync(0xffffffffu, mxa, o));
        mxb = fmaxf(mxb, __shfl_xor_sync(0xffffffffu, mxb, o));
    }
    __syncwarp();
    for (int i = lane; i < na; i += 32) sh_w[wp][i] = __expf(sh_w[wp][i] - mxa);
    for (int i = lane; i < nb; i += 32) sh_w[wp][CAP + i] = __expf(sh_w[wp][CAP + i] - mxb);
    __syncwarp();

    const float4* h4 = reinterpret_cast<const float4*>(g_h);
    float wsa = __expf(sl_a - mxa);
    float wsb = __expf(sl_b - mxb);
    float4 ha = h4[a * 32 + lane];
    float4 hb = h4[b * 32 + lane];
    float4 accA = make_float4(wsa * ha.x, wsa * ha.y, wsa * ha.z, wsa * ha.w);
    float4 accB = make_float4(wsb * hb.x, wsb * hb.y, wsb * hb.z, wsb * hb.w);
    float denA = wsa, denB = wsb;
    int nm = max(na, nb);
#pragma unroll 2
    for (int k = 0; k < nm; k++) {
        if (k < na) {
            int s = sh_s[wp][k];
            float wt = sh_w[wp][k];
            float4 hv = h4[s * 32 + lane];
            denA += wt;
            accA.x += wt * hv.x; accA.y += wt * hv.y; accA.z += wt * hv.z; accA.w += wt * hv.w;
        }
        if (k < nb) {
            int s = sh_s[wp][CAP + k];
            float wt = sh_w[wp][CAP + k];
            float4 hv = h4[s * 32 + lane];
            denB += wt;
            accB.x += wt * hv.x; accB.y += wt * hv.y; accB.z += wt * hv.z; accB.w += wt * hv.w;
        }
    }
    float iA = 1.f / denA, iB = 1.f / denB;
    float4 bv = reinterpret_cast<const float4*>(bias)[lane];
    float4 v;
    v.x = fmaxf(fmaxf(accA.x * iA, accB.x * iB) + bv.x, 0.f);
    v.y = fmaxf(fmaxf(accA.y * iA, accB.y * iB) + bv.y, 0.f);
    v.z = fmaxf(fmaxf(accA.z * iA, accB.z * iB) + bv.z, 0.f);
    v.w = fmaxf(fmaxf(accA.w * iA, accB.w * iB) + bv.w, 0.f);
    reinterpret_cast<float4*>(g_x)[j * 32 + lane] = v;

    int c = lane * 4;
    atomicAdd(&ssum[c], v.x);     atomicAdd(&ssq[c], v.x * v.x);
    atomicAdd(&ssum[c + 1], v.y); atomicAdd(&ssq[c + 1], v.y * v.y);
    atomicAdd(&ssum[c + 2], v.z); atomicAdd(&ssq[c + 2], v.z * v.z);
    atomicAdd(&ssum[c + 3], v.w); atomicAdd(&ssq[c + 3], v.w * v.w);
    __syncthreads();
    if (t < 128) {
        atomicAdd(&sums[t], ssum[t]);
        atomicAdd(&sumsq[t], ssq[t]);
    }
}

__global__ void bn_apply_kernel(int Mout, float* __restrict__ outp,
                                const float* __restrict__ sums, const float* __restrict__ sumsq) {
    int idx = blockIdx.x * blockDim.x + threadIdx.x;
    if (idx >= Mout * 128) return;
    int c = idx & 127;
    float inv = 1.f / (float)Mout;
    float mu = sums[c] * inv;
    float var = sumsq[c] * inv - mu * mu;
    outp[idx] = (g_x[idx] - mu) * rsqrtf(var + 1e-5f);
}

// ---------------- launch ----------------
extern "C" void kernel_launch(void* const* d_in, const int* in_sizes, int n_in,
                              void* d_out, int out_size) {
    const float* x    = (const float*)d_in[0];
    const float* W0   = (const float*)d_in[1];
    const float* W1   = (const float*)d_in[2];
    const float* W2   = (const float*)d_in[3];
    const float* as_  = (const float*)d_in[4];
    const float* ad_  = (const float*)d_in[5];
    const float* bias = (const float*)d_in[6];
    const int*   ei   = (const int*)d_in[7];
    float* out = (float*)d_out;

    float* sum_p; float* ssq_p;
    cudaGetSymbolAddress((void**)&sum_p, g_sum);
    cudaGetSymbolAddress((void**)&ssq_p, g_sumsq);

    cudaFuncSetAttribute(tgemm_att_kernel<64, false>,
                         cudaFuncAttributeMaxDynamicSharedMemorySize, GEMM_SMEM);
    cudaFuncSetAttribute(tgemm_att_kernel<128, true>,
                         cudaFuncAttributeMaxDynamicSharedMemorySize, GEMM_SMEM);

    static cudaStream_t side = nullptr;
    static cudaEvent_t e0 = nullptr, e1 = nullptr;
    if (!side) {
        cudaStreamCreateWithFlags(&side, cudaStreamNonBlocking);
        cudaEventCreateWithFlags(&e0, cudaEventDisableTiming);
        cudaEventCreateWithFlags(&e1, cudaEventDisableTiming);
    }

    // fork: CSR build on side stream, concurrent with layer-0 GEMM
    cudaEventRecord(e0, 0);
    cudaStreamWaitEvent(side, e0, 0);
    clear_kernel<<<(BM_TOT + 255) / 256, 256, 0, side>>>();
    build_csr_kernel<<<E0 / 256, 256, 0, side>>>(ei);
    cudaEventRecord(e1, side);

    // layer 0
    tgemm_att_kernel<64, false><<<M0 / 128, 256, GEMM_SMEM>>>(x, W0, as_, ad_,
                                                              nullptr, nullptr, 0.f);
    cudaStreamWaitEvent(0, e1, 0);
    aggregate_pool_kernel<<<16384 / 8, 256>>>(0, bias, sum_p, ssq_p);

    // layer 1
    tgemm_att_kernel<128, true><<<16384 / 128, 256, GEMM_SMEM>>>(nullptr, W1, as_ + 128, ad_ + 128,
                                                                 sum_p, ssq_p, 1.f / 16384.f);
    aggregate_pool_kernel<<<8192 / 8, 256>>>(M0, bias + 128, sum_p + 128, ssq_p + 128);

    // layer 2
    tgemm_att_kernel<128, true><<<8192 / 128, 256, GEMM_SMEM>>>(nullptr, W2, as_ + 256, ad_ + 256,
                                                                sum_p + 128, ssq_p + 128, 1.f / 8192.f);
    aggregate_pool_kernel<<<4096 / 8, 256>>>(M0 + M0 / 2, bias + 256, sum_p + 256, ssq_p + 256);

    // final BN -> output
    bn_apply_kernel<<<(4096 * 128) / 256, 256>>>(4096, out, sum_p + 256, ssq_p + 256);
}

// round 12
// speedup vs baseline: 2.8388x; 1.1828x over previous
#include <cuda_runtime.h>
#include <cuda_bf16.h>
#include <mma.h>
#include <math.h>
#include <stdint.h>

using namespace nvcuda;

static constexpr int M0 = 32768;     // B*N nodes at layer 0
static constexpr int E0 = 262144;    // edges
static constexpr int CAP = 96;       // bucket capacity
static constexpr int CNT_TOT = M0 + M0 / 2 + M0 / 4;
static constexpr int BM0_WORDS = (16384 * 512) / 32;
static constexpr int BM1_WORDS = (8192 * 256) / 32;
static constexpr int BM_TOT = BM0_WORDS + BM1_WORDS;

// ---------------- device scratch ----------------
__device__ float g_h[M0 * 128];
__device__ float g_x[(M0 / 2) * 128];
__device__ float g_es[M0];
__device__ float g_ed[M0];
__device__ int g_adj[CNT_TOT * CAP];
__device__ int g_cnt[CNT_TOT];
__device__ unsigned g_bitmap[BM_TOT];
__device__ float g_sum[3][128];
__device__ float g_sumsq[3][128];

__device__ __forceinline__ float lrelu(float x) { return x > 0.f ? x : 0.2f * x; }

// ---------------- setup ----------------

__global__ void clear_kernel() {
    int i = blockIdx.x * blockDim.x + threadIdx.x;
    if (i < BM_TOT) g_bitmap[i] = 0u;
    if (i < CNT_TOT) g_cnt[i] = 0;
    if (i < 3 * 128) { (&g_sum[0][0])[i] = 0.f; (&g_sumsq[0][0])[i] = 0.f; }
}

__global__ void build_csr_kernel(const int* __restrict__ ei) {
    int e = blockIdx.x * blockDim.x + threadIdx.x;
    if (e >= E0) return;
    int s0 = ei[e];
    int d0 = ei[E0 + e];
    if (s0 == d0) return;
    int p = atomicAdd(&g_cnt[d0], 1);
    if (p < CAP) g_adj[d0 * CAP + p] = s0;
    int s1 = s0 >> 1, d1 = d0 >> 1;
    if (s1 == d1) return;
    unsigned key1 = (unsigned)s1 * 512u + (unsigned)(d1 & 511);
    unsigned bit1 = 1u << (key1 & 31);
    if (!(atomicOr(&g_bitmap[key1 >> 5], bit1) & bit1)) {
        p = atomicAdd(&g_cnt[M0 + d1], 1);
        if (p < CAP) g_adj[(M0 + d1) * CAP + p] = s1;
    }
    int s2 = s1 >> 1, d2 = d1 >> 1;
    if (s2 == d2) return;
    unsigned key2 = (unsigned)s2 * 256u + (unsigned)(d2 & 255);
    unsigned bit2 = 1u << (key2 & 31);
    if (!(atomicOr(&g_bitmap[BM0_WORDS + (key2 >> 5)], bit2) & bit2)) {
        p = atomicAdd(&g_cnt[M0 + M0 / 2 + d2], 1);
        if (p < CAP) g_adj[(M0 + M0 / 2 + d2) * CAP + p] = s2;
    }
}

// ---------------- WMMA bf16x3 GEMM (+BN-on-load, +attention epilogue) ----------------
// D = Xhi*Whi + Xhi*Wlo + Xlo*Whi  (split-precision, ~2e-5 rel err)
// block: 256 threads / 8 warps; tile 128x128; warp tile 32x64 (2x4 of 16x16 frags).
// smem tiles use NON-power-of-2 row strides to kill LDSM bank conflicts:
//   X: ld=40 bf16 (80B stride), W: ld=136 bf16 (272B stride).
static constexpr int XLD = 40;    // X tile leading dim (elements)
static constexpr int WLD = 136;   // W tile leading dim (elements)
static constexpr int GEMM_SMEM = 128 * 132 * 4;   // 67584 (covers tiles: 2*10240+2*8704=37888)

__device__ __forceinline__ void split_pack(float a, float b, uint32_t& hi, uint32_t& lo) {
    __nv_bfloat16 h0 = __float2bfloat16(a), h1 = __float2bfloat16(b);
    __nv_bfloat16 l0 = __float2bfloat16(a - __bfloat162float(h0));
    __nv_bfloat16 l1 = __float2bfloat16(b - __bfloat162float(h1));
    hi = ((uint32_t)*(uint16_t*)&h1 << 16) | *(uint16_t*)&h0;
    lo = ((uint32_t)*(uint16_t*)&l1 << 16) | *(uint16_t*)&l0;
}

template <int FIN, bool DO_BN>
__global__ void __launch_bounds__(256)
tgemm_att_kernel(const float* __restrict__ Xp, const float* __restrict__ W,
                 const float* __restrict__ a_s, const float* __restrict__ a_d,
                 const float* __restrict__ sums, const float* __restrict__ sumsq,
                 float inv_count) {
    extern __shared__ char smem[];
    __shared__ float sAS[128], sAD[128], sMU[128], sIS[128];
    __nv_bfloat16* Xhi = reinterpret_cast<__nv_bfloat16*>(smem);
    __nv_bfloat16* Xlo = Xhi + 128 * XLD;
    __nv_bfloat16* Whi = Xlo + 128 * XLD;
    __nv_bfloat16* Wlo = Whi + 32 * WLD;
    float* stg = reinterpret_cast<float*>(smem);

    int t = threadIdx.x;
    int w = t >> 5;
    int r0 = blockIdx.x * 128;
    const float* X = Xp ? Xp : g_x;

    if (t < 128) {
        sAS[t] = a_s[t];
        sAD[t] = a_d[t];
        if (DO_BN) {
            float mu = sums[t] * inv_count;
            float var = sumsq[t] * inv_count - mu * mu;
            sMU[t] = mu;
            sIS[t] = rsqrtf(var + 1e-5f);
        }
    }
    __syncthreads();

    int wm = w >> 1, wn = w & 1;   // warp tile: rows [wm*32,+32), cols [wn*64,+64)
    wmma::fragment<wmma::accumulator, 16, 16, 16, float> acc[2][4];
#pragma unroll
    for (int mi = 0; mi < 2; mi++)
#pragma unroll
        for (int ni = 0; ni < 4; ni++) wmma::fill_fragment(acc[mi][ni], 0.f);

    for (int k0 = 0; k0 < FIN; k0 += 32) {
        // X tile: 128 rows x 32 cols -> Xhi/Xlo (ld XLD)
#pragma unroll
        for (int i = 0; i < 4; i++) {
            int e = t + 256 * i;           // 0..1023
            int row = e >> 3, c4 = e & 7;
            float4 v = *reinterpret_cast<const float4*>(&X[(size_t)(r0 + row) * FIN + k0 + c4 * 4]);
            if (DO_BN) {
                int cb = k0 + c4 * 4;
                v.x = (v.x - sMU[cb]) * sIS[cb];
                v.y = (v.y - sMU[cb + 1]) * sIS[cb + 1];
                v.z = (v.z - sMU[cb + 2]) * sIS[cb + 2];
                v.w = (v.w - sMU[cb + 3]) * sIS[cb + 3];
            }
            uint32_t h01, l01, h23, l23;
            split_pack(v.x, v.y, h01, l01);
            split_pack(v.z, v.w, h23, l23);
            int idx = row * XLD + c4 * 4;
            *reinterpret_cast<uint32_t*>(&Xhi[idx]) = h01;
            *reinterpret_cast<uint32_t*>(&Xhi[idx + 2]) = h23;
            *reinterpret_cast<uint32_t*>(&Xlo[idx]) = l01;
            *reinterpret_cast<uint32_t*>(&Xlo[idx + 2]) = l23;
        }
        // W tile: 32 rows x 128 cols -> Whi/Wlo (ld WLD)
#pragma unroll
        for (int i = 0; i < 4; i++) {
            int e = t + 256 * i;           // 0..1023
            int r = e >> 5, c4 = e & 31;
            float4 v = *reinterpret_cast<const float4*>(&W[(size_t)(k0 + r) * 128 + c4 * 4]);
            uint32_t h01, l01, h23, l23;
            split_pack(v.x, v.y, h01, l01);
            split_pack(v.z, v.w, h23, l23);
            int idx = r * WLD + c4 * 4;
            *reinterpret_cast<uint32_t*>(&Whi[idx]) = h01;
            *reinterpret_cast<uint32_t*>(&Whi[idx + 2]) = h23;
            *reinterpret_cast<uint32_t*>(&Wlo[idx]) = l01;
            *reinterpret_cast<uint32_t*>(&Wlo[idx + 2]) = l23;
        }
        __syncthreads();

#pragma unroll
        for (int kk = 0; kk < 32; kk += 16) {
            wmma::fragment<wmma::matrix_a, 16, 16, 16, __nv_bfloat16, wmma::row_major> ahi[2], alo[2];
            wmma::fragment<wmma::matrix_b, 16, 16, 16, __nv_bfloat16, wmma::row_major> bhi[4], blo[4];
#pragma unroll
            for (int mi = 0; mi < 2; mi++) {
                const __nv_bfloat16* pa = Xhi + (wm * 32 + mi * 16) * XLD + kk;
                wmma::load_matrix_sync(ahi[mi], pa, XLD);
                wmma::load_matrix_sync(alo[mi], pa + 128 * XLD, XLD);   // Xlo
            }
#pragma unroll
            for (int ni = 0; ni < 4; ni++) {
                const __nv_bfloat16* pb = Whi + kk * WLD + wn * 64 + ni * 16;
                wmma::load_matrix_sync(bhi[ni], pb, WLD);
                wmma::load_matrix_sync(blo[ni], pb + 32 * WLD, WLD);    // Wlo
            }
#pragma unroll
            for (int mi = 0; mi < 2; mi++)
#pragma unroll
                for (int ni = 0; ni < 4; ni++) {
                    wmma::mma_sync(acc[mi][ni], ahi[mi], bhi[ni], acc[mi][ni]);
                    wmma::mma_sync(acc[mi][ni], ahi[mi], blo[ni], acc[mi][ni]);
                    wmma::mma_sync(acc[mi][ni], alo[mi], bhi[ni], acc[mi][ni]);
                }
        }
        __syncthreads();
    }

    // ---- epilogue: stage f32 rows (ld 132 -> conflict-free col walks) ----
#pragma unroll
    for (int mi = 0; mi < 2; mi++)
#pragma unroll
        for (int ni = 0; ni < 4; ni++)
            wmma::store_matrix_sync(stg + (wm * 32 + mi * 16) * 132 + wn * 64 + ni * 16,
                                    acc[mi][ni], 132, wmma::mem_row_major);
    __syncthreads();

    // es/ed: thread t<128 owns row t (33-float4 stride -> conflict-free)
    if (t < 128) {
        const float4* row4 = reinterpret_cast<const float4*>(stg) + t * 33;
        const float4* as4 = reinterpret_cast<const float4*>(sAS);
        const float4* ad4 = reinterpret_cast<const float4*>(sAD);
        float es = 0.f, ed = 0.f;
#pragma unroll
        for (int c = 0; c < 32; c++) {
            float4 v = row4[c];
            float4 a = as4[c];
            float4 d = ad4[c];
            es += v.x * a.x + v.y * a.y + v.z * a.z + v.w * a.w;
            ed += v.x * d.x + v.y * d.y + v.z * d.z + v.w * d.w;
        }
        g_es[r0 + t] = es;
        g_ed[r0 + t] = ed;
    }
    // coalesced copy staging -> g_h
#pragma unroll
    for (int i = 0; i < 16; i++) {
        int e4 = t + 256 * i;                 // 0..4095
        int row = e4 >> 5, c4 = e4 & 31;
        reinterpret_cast<float4*>(&g_h[(size_t)(r0 + row) * 128])[c4] =
            reinterpret_cast<const float4*>(stg + row * 132)[c4];
    }
}

// ---------------- fused aggregate + pool + bias + relu + BN stats ----------------
__global__ void __launch_bounds__(256) aggregate_pool_kernel(
        int cbase, const float* __restrict__ bias,
        float* __restrict__ sums, float* __restrict__ sumsq) {
    __shared__ int sh_s[8][2 * CAP];
    __shared__ float sh_w[8][2 * CAP];
    __shared__ float ssum[128], ssq[128];
    int t = threadIdx.x;
    int wp = t >> 5;
    int lane = t & 31;
    if (t < 128) { ssum[t] = 0.f; ssq[t] = 0.f; }
    int j = blockIdx.x * 8 + wp;
    int a = 2 * j, b = a + 1;

    int na = min(g_cnt[cbase + a], CAP);
    int nb = min(g_cnt[cbase + b], CAP);
    int base_a = (cbase + a) * CAP;
    int base_b = (cbase + b) * CAP;
    float ed_a = g_ed[a], ed_b = g_ed[b];
    float sl_a = lrelu(g_es[a] + ed_a);
    float sl_b = lrelu(g_es[b] + ed_b);

    float mxa = sl_a, mxb = sl_b;
    for (int i = lane; i < na; i += 32) {
        int s = g_adj[base_a + i];
        float lg = lrelu(g_es[s] + ed_a);
        sh_s[wp][i] = s;
        sh_w[wp][i] = lg;
        mxa = fmaxf(mxa, lg);
    }
    for (int i = lane; i < nb; i += 32) {
        int s = g_adj[base_b + i];
        float lg = lrelu(g_es[s] + ed_b);
        sh_s[wp][CAP + i] = s;
        sh_w[wp][CAP + i] = lg;
        mxb = fmaxf(mxb, lg);
    }
#pragma unroll
    for (int o = 16; o; o >>= 1) {
        mxa = fmaxf(mxa, __shfl_xor_sync(0xffffffffu, mxa, o));
        mxb = fmaxf(mxb, __shfl_xor_sync(0xffffffffu, mxb, o));
    }
    __syncwarp();
    for (int i = lane; i < na; i += 32) sh_w[wp][i] = __expf(sh_w[wp][i] - mxa);
    for (int i = lane; i < nb; i += 32) sh_w[wp][CAP + i] = __expf(sh_w[wp][CAP + i] - mxb);
    __syncwarp();

    const float4* h4 = reinterpret_cast<const float4*>(g_h);
    float wsa = __expf(sl_a - mxa);
    float wsb = __expf(sl_b - mxb);
    float4 ha = h4[a * 32 + lane];
    float4 hb = h4[b * 32 + lane];
    float4 accA = make_float4(wsa * ha.x, wsa * ha.y, wsa * ha.z, wsa * ha.w);
    float4 accB = make_float4(wsb * hb.x, wsb * hb.y, wsb * hb.z, wsb * hb.w);
    float denA = wsa, denB = wsb;
    int nm = max(na, nb);
#pragma unroll 2
    for (int k = 0; k < nm; k++) {
        if (k < na) {
            int s = sh_s[wp][k];
            float wt = sh_w[wp][k];
            float4 hv = h4[s * 32 + lane];
            denA += wt;
            accA.x += wt * hv.x; accA.y += wt * hv.y; accA.z += wt * hv.z; accA.w += wt * hv.w;
        }
        if (k < nb) {
            int s = sh_s[wp][CAP + k];
            float wt = sh_w[wp][CAP + k];
            float4 hv = h4[s * 32 + lane];
            denB += wt;
            accB.x += wt * hv.x; accB.y += wt * hv.y; accB.z += wt * hv.z; accB.w += wt * hv.w;
        }
    }
    float iA = 1.f / denA, iB = 1.f / denB;
    float4 bv = reinterpret_cast<const float4*>(bias)[lane];
    float4 v;
    v.x = fmaxf(fmaxf(accA.x * iA, accB.x * iB) + bv.x, 0.f);
    v.y = fmaxf(fmaxf(accA.y * iA, accB.y * iB) + bv.y, 0.f);
    v.z = fmaxf(fmaxf(accA.z * iA, accB.z * iB) + bv.z, 0.f);
    v.w = fmaxf(fmaxf(accA.w * iA, accB.w * iB) + bv.w, 0.f);
    reinterpret_cast<float4*>(g_x)[j * 32 + lane] = v;

    int c = lane * 4;
    atomicAdd(&ssum[c], v.x);     atomicAdd(&ssq[c], v.x * v.x);
    atomicAdd(&ssum[c + 1], v.y); atomicAdd(&ssq[c + 1], v.y * v.y);
    atomicAdd(&ssum[c + 2], v.z); atomicAdd(&ssq[c + 2], v.z * v.z);
    atomicAdd(&ssum[c + 3], v.w); atomicAdd(&ssq[c + 3], v.w * v.w);
    __syncthreads();
    if (t < 128) {
        atomicAdd(&sums[t], ssum[t]);
        atomicAdd(&sumsq[t], ssq[t]);
    }
}

__global__ void bn_apply_kernel(int Mout, float* __restrict__ outp,
                                const float* __restrict__ sums, const float* __restrict__ sumsq) {
    int idx = blockIdx.x * blockDim.x + threadIdx.x;
    if (idx >= Mout * 128) return;
    int c = idx & 127;
    float inv = 1.f / (float)Mout;
    float mu = sums[c] * inv;
    float var = sumsq[c] * inv - mu * mu;
    outp[idx] = (g_x[idx] - mu) * rsqrtf(var + 1e-5f);
}

// ---------------- launch ----------------
extern "C" void kernel_launch(void* const* d_in, const int* in_sizes, int n_in,
                              void* d_out, int out_size) {
    const float* x    = (const float*)d_in[0];
    const float* W0   = (const float*)d_in[1];
    const float* W1   = (const float*)d_in[2];
    const float* W2   = (const float*)d_in[3];
    const float* as_  = (const float*)d_in[4];
    const float* ad_  = (const float*)d_in[5];
    const float* bias = (const float*)d_in[6];
    const int*   ei   = (const int*)d_in[7];
    float* out = (float*)d_out;

    float* sum_p; float* ssq_p;
    cudaGetSymbolAddress((void**)&sum_p, g_sum);
    cudaGetSymbolAddress((void**)&ssq_p, g_sumsq);

    cudaFuncSetAttribute(tgemm_att_kernel<64, false>,
                         cudaFuncAttributeMaxDynamicSharedMemorySize, GEMM_SMEM);
    cudaFuncSetAttribute(tgemm_att_kernel<128, true>,
                         cudaFuncAttributeMaxDynamicSharedMemorySize, GEMM_SMEM);

    static cudaStream_t side = nullptr;
    static cudaEvent_t e0 = nullptr, e1 = nullptr;
    if (!side) {
        cudaStreamCreateWithFlags(&side, cudaStreamNonBlocking);
        cudaEventCreateWithFlags(&e0, cudaEventDisableTiming);
        cudaEventCreateWithFlags(&e1, cudaEventDisableTiming);
    }

    // fork: CSR build on side stream, concurrent with layer-0 GEMM
    cudaEventRecord(e0, 0);
    cudaStreamWaitEvent(side, e0, 0);
    clear_kernel<<<(BM_TOT + 255) / 256, 256, 0, side>>>();
    build_csr_kernel<<<E0 / 256, 256, 0, side>>>(ei);
    cudaEventRecord(e1, side);

    // layer 0
    tgemm_att_kernel<64, false><<<M0 / 128, 256, GEMM_SMEM>>>(x, W0, as_, ad_,
                                                              nullptr, nullptr, 0.f);
    cudaStreamWaitEvent(0, e1, 0);
    aggregate_pool_kernel<<<16384 / 8, 256>>>(0, bias, sum_p, ssq_p);

    // layer 1
    tgemm_att_kernel<128, true><<<16384 / 128, 256, GEMM_SMEM>>>(nullptr, W1, as_ + 128, ad_ + 128,
                                                                 sum_p, ssq_p, 1.f / 16384.f);
    aggregate_pool_kernel<<<8192 / 8, 256>>>(M0, bias + 128, sum_p + 128, ssq_p + 128);

    // layer 2
    tgemm_att_kernel<128, true><<<8192 / 128, 256, GEMM_SMEM>>>(nullptr, W2, as_ + 256, ad_ + 256,
                                                                sum_p + 128, ssq_p + 128, 1.f / 8192.f);
    aggregate_pool_kernel<<<4096 / 8, 256>>>(M0 + M0 / 2, bias + 256, sum_p + 256, ssq_p + 256);

    // final BN -> output
    bn_apply_kernel<<<(4096 * 128) / 256, 256>>>(4096, out, sum_p + 256, ssq_p + 256);
}

// round 13
// speedup vs baseline: 2.9642x; 1.0442x over previous
#include <cuda_runtime.h>
#include <cuda_bf16.h>
#include <mma.h>
#include <math.h>
#include <stdint.h>

using namespace nvcuda;

static constexpr int M0 = 32768;     // B*N nodes at layer 0
static constexpr int E0 = 262144;    // edges
static constexpr int CAP = 96;       // bucket capacity
static constexpr int CNT_TOT = M0 + M0 / 2 + M0 / 4;
static constexpr int BM0_WORDS = (16384 * 512) / 32;
static constexpr int BM1_WORDS = (8192 * 256) / 32;
static constexpr int BM_TOT = BM0_WORDS + BM1_WORDS;

// ---------------- device scratch ----------------
__device__ float g_h[M0 * 128];
__device__ float g_x[(M0 / 2) * 128];
__device__ float g_es[M0];
__device__ float g_ed[M0];
__device__ int g_adj[CNT_TOT * CAP];
__device__ int g_cnt[CNT_TOT];
__device__ unsigned g_bitmap[BM_TOT];
__device__ float g_sum[3][128];
__device__ float g_sumsq[3][128];

__device__ __forceinline__ float lrelu(float x) { return x > 0.f ? x : 0.2f * x; }

// ---------------- setup ----------------

__global__ void clear_kernel() {
    int i = blockIdx.x * blockDim.x + threadIdx.x;
    if (i < BM_TOT) g_bitmap[i] = 0u;
    if (i < CNT_TOT) g_cnt[i] = 0;
    if (i < 3 * 128) { (&g_sum[0][0])[i] = 0.f; (&g_sumsq[0][0])[i] = 0.f; }
}

__global__ void build_csr_kernel(const int* __restrict__ ei) {
    int e = blockIdx.x * blockDim.x + threadIdx.x;
    if (e >= E0) return;
    int s0 = ei[e];
    int d0 = ei[E0 + e];
    if (s0 == d0) return;
    int p = atomicAdd(&g_cnt[d0], 1);
    if (p < CAP) g_adj[d0 * CAP + p] = s0;
    int s1 = s0 >> 1, d1 = d0 >> 1;
    if (s1 == d1) return;
    unsigned key1 = (unsigned)s1 * 512u + (unsigned)(d1 & 511);
    unsigned bit1 = 1u << (key1 & 31);
    if (!(atomicOr(&g_bitmap[key1 >> 5], bit1) & bit1)) {
        p = atomicAdd(&g_cnt[M0 + d1], 1);
        if (p < CAP) g_adj[(M0 + d1) * CAP + p] = s1;
    }
    int s2 = s1 >> 1, d2 = d1 >> 1;
    if (s2 == d2) return;
    unsigned key2 = (unsigned)s2 * 256u + (unsigned)(d2 & 255);
    unsigned bit2 = 1u << (key2 & 31);
    if (!(atomicOr(&g_bitmap[BM0_WORDS + (key2 >> 5)], bit2) & bit2)) {
        p = atomicAdd(&g_cnt[M0 + M0 / 2 + d2], 1);
        if (p < CAP) g_adj[(M0 + M0 / 2 + d2) * CAP + p] = s2;
    }
}

// ---------------- WMMA bf16x3 GEMM (+BN-on-load, +attention epilogue) ----------------
static constexpr int XLD = 40;    // X tile leading dim (elements)
static constexpr int WLD = 136;   // W tile leading dim (elements)
static constexpr int GEMM_SMEM = 128 * 132 * 4;   // 67584

__device__ __forceinline__ void split_pack(float a, float b, uint32_t& hi, uint32_t& lo) {
    __nv_bfloat16 h0 = __float2bfloat16(a), h1 = __float2bfloat16(b);
    __nv_bfloat16 l0 = __float2bfloat16(a - __bfloat162float(h0));
    __nv_bfloat16 l1 = __float2bfloat16(b - __bfloat162float(h1));
    hi = ((uint32_t)*(uint16_t*)&h1 << 16) | *(uint16_t*)&h0;
    lo = ((uint32_t)*(uint16_t*)&l1 << 16) | *(uint16_t*)&l0;
}

template <int FIN, bool DO_BN>
__global__ void __launch_bounds__(256)
tgemm_att_kernel(const float* __restrict__ Xp, const float* __restrict__ W,
                 const float* __restrict__ a_s, const float* __restrict__ a_d,
                 const float* __restrict__ sums, const float* __restrict__ sumsq,
                 float inv_count) {
    extern __shared__ char smem[];
    __shared__ float sAS[128], sAD[128], sMU[128], sIS[128];
    __nv_bfloat16* Xhi = reinterpret_cast<__nv_bfloat16*>(smem);
    __nv_bfloat16* Xlo = Xhi + 128 * XLD;
    __nv_bfloat16* Whi = Xlo + 128 * XLD;
    __nv_bfloat16* Wlo = Whi + 32 * WLD;
    float* stg = reinterpret_cast<float*>(smem);

    int t = threadIdx.x;
    int w = t >> 5;
    int r0 = blockIdx.x * 128;
    const float* X = Xp ? Xp : g_x;

    if (t < 128) {
        sAS[t] = a_s[t];
        sAD[t] = a_d[t];
        if (DO_BN) {
            float mu = sums[t] * inv_count;
            float var = sumsq[t] * inv_count - mu * mu;
            sMU[t] = mu;
            sIS[t] = rsqrtf(var + 1e-5f);
        }
    }
    __syncthreads();

    int wm = w >> 1, wn = w & 1;
    wmma::fragment<wmma::accumulator, 16, 16, 16, float> acc[2][4];
#pragma unroll
    for (int mi = 0; mi < 2; mi++)
#pragma unroll
        for (int ni = 0; ni < 4; ni++) wmma::fill_fragment(acc[mi][ni], 0.f);

    for (int k0 = 0; k0 < FIN; k0 += 32) {
#pragma unroll
        for (int i = 0; i < 4; i++) {
            int e = t + 256 * i;
            int row = e >> 3, c4 = e & 7;
            float4 v = *reinterpret_cast<const float4*>(&X[(size_t)(r0 + row) * FIN + k0 + c4 * 4]);
            if (DO_BN) {
                int cb = k0 + c4 * 4;
                v.x = (v.x - sMU[cb]) * sIS[cb];
                v.y = (v.y - sMU[cb + 1]) * sIS[cb + 1];
                v.z = (v.z - sMU[cb + 2]) * sIS[cb + 2];
                v.w = (v.w - sMU[cb + 3]) * sIS[cb + 3];
            }
            uint32_t h01, l01, h23, l23;
            split_pack(v.x, v.y, h01, l01);
            split_pack(v.z, v.w, h23, l23);
            int idx = row * XLD + c4 * 4;
            *reinterpret_cast<uint32_t*>(&Xhi[idx]) = h01;
            *reinterpret_cast<uint32_t*>(&Xhi[idx + 2]) = h23;
            *reinterpret_cast<uint32_t*>(&Xlo[idx]) = l01;
            *reinterpret_cast<uint32_t*>(&Xlo[idx + 2]) = l23;
        }
#pragma unroll
        for (int i = 0; i < 4; i++) {
            int e = t + 256 * i;
            int r = e >> 5, c4 = e & 31;
            float4 v = *reinterpret_cast<const float4*>(&W[(size_t)(k0 + r) * 128 + c4 * 4]);
            uint32_t h01, l01, h23, l23;
            split_pack(v.x, v.y, h01, l01);
            split_pack(v.z, v.w, h23, l23);
            int idx = r * WLD + c4 * 4;
            *reinterpret_cast<uint32_t*>(&Whi[idx]) = h01;
            *reinterpret_cast<uint32_t*>(&Whi[idx + 2]) = h23;
            *reinterpret_cast<uint32_t*>(&Wlo[idx]) = l01;
            *reinterpret_cast<uint32_t*>(&Wlo[idx + 2]) = l23;
        }
        __syncthreads();

#pragma unroll
        for (int kk = 0; kk < 32; kk += 16) {
            wmma::fragment<wmma::matrix_a, 16, 16, 16, __nv_bfloat16, wmma::row_major> ahi[2], alo[2];
            wmma::fragment<wmma::matrix_b, 16, 16, 16, __nv_bfloat16, wmma::row_major> bhi[4], blo[4];
#pragma unroll
            for (int mi = 0; mi < 2; mi++) {
                const __nv_bfloat16* pa = Xhi + (wm * 32 + mi * 16) * XLD + kk;
                wmma::load_matrix_sync(ahi[mi], pa, XLD);
                wmma::load_matrix_sync(alo[mi], pa + 128 * XLD, XLD);
            }
#pragma unroll
            for (int ni = 0; ni < 4; ni++) {
                const __nv_bfloat16* pb = Whi + kk * WLD + wn * 64 + ni * 16;
                wmma::load_matrix_sync(bhi[ni], pb, WLD);
                wmma::load_matrix_sync(blo[ni], pb + 32 * WLD, WLD);
            }
#pragma unroll
            for (int mi = 0; mi < 2; mi++)
#pragma unroll
                for (int ni = 0; ni < 4; ni++) {
                    wmma::mma_sync(acc[mi][ni], ahi[mi], bhi[ni], acc[mi][ni]);
                    wmma::mma_sync(acc[mi][ni], ahi[mi], blo[ni], acc[mi][ni]);
                    wmma::mma_sync(acc[mi][ni], alo[mi], bhi[ni], acc[mi][ni]);
                }
        }
        __syncthreads();
    }

#pragma unroll
    for (int mi = 0; mi < 2; mi++)
#pragma unroll
        for (int ni = 0; ni < 4; ni++)
            wmma::store_matrix_sync(stg + (wm * 32 + mi * 16) * 132 + wn * 64 + ni * 16,
                                    acc[mi][ni], 132, wmma::mem_row_major);
    __syncthreads();

    if (t < 128) {
        const float4* row4 = reinterpret_cast<const float4*>(stg) + t * 33;
        const float4* as4 = reinterpret_cast<const float4*>(sAS);
        const float4* ad4 = reinterpret_cast<const float4*>(sAD);
        float es = 0.f, ed = 0.f;
#pragma unroll
        for (int c = 0; c < 32; c++) {
            float4 v = row4[c];
            float4 a = as4[c];
            float4 d = ad4[c];
            es += v.x * a.x + v.y * a.y + v.z * a.z + v.w * a.w;
            ed += v.x * d.x + v.y * d.y + v.z * d.z + v.w * d.w;
        }
        g_es[r0 + t] = es;
        g_ed[r0 + t] = ed;
    }
#pragma unroll
    for (int i = 0; i < 16; i++) {
        int e4 = t + 256 * i;
        int row = e4 >> 5, c4 = e4 & 31;
        reinterpret_cast<float4*>(&g_h[(size_t)(r0 + row) * 128])[c4] =
            reinterpret_cast<const float4*>(stg + row * 132)[c4];
    }
}

// ---------------- fused aggregate + pool + bias + relu + BN stats ----------------
// warp per pool pair; BN stats via conflict-free per-warp stores + tree reduce (NO smem atomics)
__global__ void __launch_bounds__(256) aggregate_pool_kernel(
        int cbase, const float* __restrict__ bias,
        float* __restrict__ sums, float* __restrict__ sumsq) {
    __shared__ int sh_s[8][2 * CAP];
    __shared__ float sh_w[8][2 * CAP];
    __shared__ float psum[8][128];
    __shared__ float psq[8][128];
    int t = threadIdx.x;
    int wp = t >> 5;
    int lane = t & 31;
    int j = blockIdx.x * 8 + wp;
    int a = 2 * j, b = a + 1;

    int na = min(g_cnt[cbase + a], CAP);
    int nb = min(g_cnt[cbase + b], CAP);
    int base_a = (cbase + a) * CAP;
    int base_b = (cbase + b) * CAP;
    float ed_a = g_ed[a], ed_b = g_ed[b];
    float sl_a = lrelu(g_es[a] + ed_a);
    float sl_b = lrelu(g_es[b] + ed_b);

    float mxa = sl_a, mxb = sl_b;
    for (int i = lane; i < na; i += 32) {
        int s = g_adj[base_a + i];
        float lg = lrelu(g_es[s] + ed_a);
        sh_s[wp][i] = s;
        sh_w[wp][i] = lg;
        mxa = fmaxf(mxa, lg);
    }
    for (int i = lane; i < nb; i += 32) {
        int s = g_adj[base_b + i];
        float lg = lrelu(g_es[s] + ed_b);
        sh_s[wp][CAP + i] = s;
        sh_w[wp][CAP + i] = lg;
        mxb = fmaxf(mxb, lg);
    }
#pragma unroll
    for (int o = 16; o; o >>= 1) {
        mxa = fmaxf(mxa, __shfl_xor_sync(0xffffffffu, mxa, o));
        mxb = fmaxf(mxb, __shfl_xor_sync(0xffffffffu, mxb, o));
    }
    __syncwarp();
    for (int i = lane; i < na; i += 32) sh_w[wp][i] = __expf(sh_w[wp][i] - mxa);
    for (int i = lane; i < nb; i += 32) sh_w[wp][CAP + i] = __expf(sh_w[wp][CAP + i] - mxb);
    __syncwarp();

    const float4* h4 = reinterpret_cast<const float4*>(g_h);
    float wsa = __expf(sl_a - mxa);
    float wsb = __expf(sl_b - mxb);
    float4 ha = h4[a * 32 + lane];
    float4 hb = h4[b * 32 + lane];
    float4 accA = make_float4(wsa * ha.x, wsa * ha.y, wsa * ha.z, wsa * ha.w);
    float4 accB = make_float4(wsb * hb.x, wsb * hb.y, wsb * hb.z, wsb * hb.w);
    float denA = wsa, denB = wsb;
    int nm = max(na, nb);
#pragma unroll 4
    for (int k = 0; k < nm; k++) {
        if (k < na) {
            int s = sh_s[wp][k];
            float wt = sh_w[wp][k];
            float4 hv = h4[s * 32 + lane];
            denA += wt;
            accA.x += wt * hv.x; accA.y += wt * hv.y; accA.z += wt * hv.z; accA.w += wt * hv.w;
        }
        if (k < nb) {
            int s = sh_s[wp][CAP + k];
            float wt = sh_w[wp][CAP + k];
            float4 hv = h4[s * 32 + lane];
            denB += wt;
            accB.x += wt * hv.x; accB.y += wt * hv.y; accB.z += wt * hv.z; accB.w += wt * hv.w;
        }
    }
    float iA = 1.f / denA, iB = 1.f / denB;
    float4 bv = reinterpret_cast<const float4*>(bias)[lane];
    float4 v;
    v.x = fmaxf(fmaxf(accA.x * iA, accB.x * iB) + bv.x, 0.f);
    v.y = fmaxf(fmaxf(accA.y * iA, accB.y * iB) + bv.y, 0.f);
    v.z = fmaxf(fmaxf(accA.z * iA, accB.z * iB) + bv.z, 0.f);
    v.w = fmaxf(fmaxf(accA.w * iA, accB.w * iB) + bv.w, 0.f);
    reinterpret_cast<float4*>(g_x)[j * 32 + lane] = v;

    // BN stats: conflict-free per-warp float4 stores, then 128-thread tree reduce
    *reinterpret_cast<float4*>(&psum[wp][lane * 4]) = v;
    *reinterpret_cast<float4*>(&psq[wp][lane * 4]) =
        make_float4(v.x * v.x, v.y * v.y, v.z * v.z, v.w * v.w);
    __syncthreads();
    if (t < 128) {
        float s = 0.f, q = 0.f;
#pragma unroll
        for (int w2 = 0; w2 < 8; w2++) { s += psum[w2][t]; q += psq[w2][t]; }
        atomicAdd(&sums[t], s);
        atomicAdd(&sumsq[t], q);
    }
}

__global__ void bn_apply_kernel(int Mout, float* __restrict__ outp,
                                const float* __restrict__ sums, const float* __restrict__ sumsq) {
    int idx = blockIdx.x * blockDim.x + threadIdx.x;
    if (idx >= Mout * 128) return;
    int c = idx & 127;
    float inv = 1.f / (float)Mout;
    float mu = sums[c] * inv;
    float var = sumsq[c] * inv - mu * mu;
    outp[idx] = (g_x[idx] - mu) * rsqrtf(var + 1e-5f);
}

// ---------------- launch ----------------
extern "C" void kernel_launch(void* const* d_in, const int* in_sizes, int n_in,
                              void* d_out, int out_size) {
    const float* x    = (const float*)d_in[0];
    const float* W0   = (const float*)d_in[1];
    const float* W1   = (const float*)d_in[2];
    const float* W2   = (const float*)d_in[3];
    const float* as_  = (const float*)d_in[4];
    const float* ad_  = (const float*)d_in[5];
    const float* bias = (const float*)d_in[6];
    const int*   ei   = (const int*)d_in[7];
    float* out = (float*)d_out;

    float* sum_p; float* ssq_p;
    cudaGetSymbolAddress((void**)&sum_p, g_sum);
    cudaGetSymbolAddress((void**)&ssq_p, g_sumsq);

    cudaFuncSetAttribute(tgemm_att_kernel<64, false>,
                         cudaFuncAttributeMaxDynamicSharedMemorySize, GEMM_SMEM);
    cudaFuncSetAttribute(tgemm_att_kernel<128, true>,
                         cudaFuncAttributeMaxDynamicSharedMemorySize, GEMM_SMEM);

    static cudaStream_t side = nullptr;
    static cudaEvent_t e0 = nullptr, e1 = nullptr;
    if (!side) {
        cudaStreamCreateWithFlags(&side, cudaStreamNonBlocking);
        cudaEventCreateWithFlags(&e0, cudaEventDisableTiming);
        cudaEventCreateWithFlags(&e1, cudaEventDisableTiming);
    }

    // fork: CSR build on side stream, concurrent with layer-0 GEMM
    cudaEventRecord(e0, 0);
    cudaStreamWaitEvent(side, e0, 0);
    clear_kernel<<<(BM_TOT + 255) / 256, 256, 0, side>>>();
    build_csr_kernel<<<E0 / 256, 256, 0, side>>>(ei);
    cudaEventRecord(e1, side);

    // layer 0
    tgemm_att_kernel<64, false><<<M0 / 128, 256, GEMM_SMEM>>>(x, W0, as_, ad_,
                                                              nullptr, nullptr, 0.f);
    cudaStreamWaitEvent(0, e1, 0);
    aggregate_pool_kernel<<<16384 / 8, 256>>>(0, bias, sum_p, ssq_p);

    // layer 1
    tgemm_att_kernel<128, true><<<16384 / 128, 256, GEMM_SMEM>>>(nullptr, W1, as_ + 128, ad_ + 128,
                                                                 sum_p, ssq_p, 1.f / 16384.f);
    aggregate_pool_kernel<<<8192 / 8, 256>>>(M0, bias + 128, sum_p + 128, ssq_p + 128);

    // layer 2
    tgemm_att_kernel<128, true><<<8192 / 128, 256, GEMM_SMEM>>>(nullptr, W2, as_ + 256, ad_ + 256,
                                                                sum_p + 128, ssq_p + 128, 1.f / 8192.f);
    aggregate_pool_kernel<<<4096 / 8, 256>>>(M0 + M0 / 2, bias + 256, sum_p + 256, ssq_p + 256);

    // final BN -> output
    bn_apply_kernel<<<(4096 * 128) / 256, 256>>>(4096, out, sum_p + 256, ssq_p + 256);
}

// round 14
// speedup vs baseline: 3.0968x; 1.0447x over previous
#include <cuda_runtime.h>
#include <cuda_bf16.h>
#include <mma.h>
#include <math.h>
#include <stdint.h>

using namespace nvcuda;

static constexpr int M0 = 32768;     // B*N nodes at layer 0
static constexpr int E0 = 262144;    // edges
static constexpr int CAP = 96;       // bucket capacity
static constexpr int CNT_TOT = M0 + M0 / 2 + M0 / 4;
static constexpr int BM0_WORDS = (16384 * 512) / 32;
static constexpr int BM1_WORDS = (8192 * 256) / 32;
static constexpr int BM_TOT = BM0_WORDS + BM1_WORDS;

// ---------------- device scratch ----------------
__device__ float g_h[M0 * 128];
__device__ float g_x[(M0 / 2) * 128];
__device__ float g_es[M0];
__device__ float g_ed[M0];
__device__ int g_adj[CNT_TOT * CAP];
__device__ int g_cnt[CNT_TOT];
__device__ unsigned g_bitmap[BM_TOT];
__device__ float g_sum[3][128];
__device__ float g_sumsq[3][128];
__device__ __align__(16) __nv_bfloat16 g_whi[2][128 * 128];   // pre-split W1, W2
__device__ __align__(16) __nv_bfloat16 g_wlo[2][128 * 128];

__device__ __forceinline__ float lrelu(float x) { return x > 0.f ? x : 0.2f * x; }

// ---------------- setup ----------------

__global__ void clear_kernel() {
    int i = blockIdx.x * blockDim.x + threadIdx.x;
    if (i < BM_TOT) g_bitmap[i] = 0u;
    if (i < CNT_TOT) g_cnt[i] = 0;
    if (i < 3 * 128) { (&g_sum[0][0])[i] = 0.f; (&g_sumsq[0][0])[i] = 0.f; }
}

__global__ void wsplit_kernel(const float* __restrict__ W,
                              __nv_bfloat16* __restrict__ hi,
                              __nv_bfloat16* __restrict__ lo) {
    int i = blockIdx.x * blockDim.x + threadIdx.x;   // 0..16383
    float v = W[i];
    __nv_bfloat16 h = __float2bfloat16(v);
    hi[i] = h;
    lo[i] = __float2bfloat16(v - __bfloat162float(h));
}

__global__ void build_csr_kernel(const int* __restrict__ ei) {
    int e = blockIdx.x * blockDim.x + threadIdx.x;
    if (e >= E0) return;
    int s0 = ei[e];
    int d0 = ei[E0 + e];
    if (s0 == d0) return;
    int p = atomicAdd(&g_cnt[d0], 1);
    if (p < CAP) g_adj[d0 * CAP + p] = s0;
    int s1 = s0 >> 1, d1 = d0 >> 1;
    if (s1 == d1) return;
    unsigned key1 = (unsigned)s1 * 512u + (unsigned)(d1 & 511);
    unsigned bit1 = 1u << (key1 & 31);
    if (!(atomicOr(&g_bitmap[key1 >> 5], bit1) & bit1)) {
        p = atomicAdd(&g_cnt[M0 + d1], 1);
        if (p < CAP) g_adj[(M0 + d1) * CAP + p] = s1;
    }
    int s2 = s1 >> 1, d2 = d1 >> 1;
    if (s2 == d2) return;
    unsigned key2 = (unsigned)s2 * 256u + (unsigned)(d2 & 255);
    unsigned bit2 = 1u << (key2 & 31);
    if (!(atomicOr(&g_bitmap[BM0_WORDS + (key2 >> 5)], bit2) & bit2)) {
        p = atomicAdd(&g_cnt[M0 + M0 / 2 + d2], 1);
        if (p < CAP) g_adj[(M0 + M0 / 2 + d2) * CAP + p] = s2;
    }
}

// ---------------- WMMA bf16x3 GEMM (+BN-on-load, +attention epilogue) ----------------
static constexpr int XLD = 40;    // X tile leading dim (elements)
static constexpr int WLD = 136;   // W tile leading dim (elements)
static constexpr int GEMM_SMEM = 128 * 132 * 4;   // 67584

__device__ __forceinline__ void split_pack(float a, float b, uint32_t& hi, uint32_t& lo) {
    __nv_bfloat16 h0 = __float2bfloat16(a), h1 = __float2bfloat16(b);
    __nv_bfloat16 l0 = __float2bfloat16(a - __bfloat162float(h0));
    __nv_bfloat16 l1 = __float2bfloat16(b - __bfloat162float(h1));
    hi = ((uint32_t)*(uint16_t*)&h1 << 16) | *(uint16_t*)&h0;
    lo = ((uint32_t)*(uint16_t*)&l1 << 16) | *(uint16_t*)&l0;
}

// PRE=true: W already split into whi_g/wlo_g (bf16); else convert from Wf on the fly.
template <int FIN, bool DO_BN, bool PRE>
__global__ void __launch_bounds__(256)
tgemm_att_kernel(const float* __restrict__ Xp, const float* __restrict__ Wf,
                 const __nv_bfloat16* __restrict__ whi_g, const __nv_bfloat16* __restrict__ wlo_g,
                 const float* __restrict__ a_s, const float* __restrict__ a_d,
                 const float* __restrict__ sums, const float* __restrict__ sumsq,
                 float inv_count) {
    extern __shared__ char smem[];
    __shared__ float sAS[128], sAD[128], sMU[128], sIS[128];
    __nv_bfloat16* Xhi = reinterpret_cast<__nv_bfloat16*>(smem);
    __nv_bfloat16* Xlo = Xhi + 128 * XLD;
    __nv_bfloat16* Whi = Xlo + 128 * XLD;
    __nv_bfloat16* Wlo = Whi + 32 * WLD;
    float* stg = reinterpret_cast<float*>(smem);

    int t = threadIdx.x;
    int w = t >> 5;
    int r0 = blockIdx.x * 128;
    const float* X = Xp ? Xp : g_x;

    if (t < 128) {
        sAS[t] = a_s[t];
        sAD[t] = a_d[t];
        if (DO_BN) {
            float mu = sums[t] * inv_count;
            float var = sumsq[t] * inv_count - mu * mu;
            sMU[t] = mu;
            sIS[t] = rsqrtf(var + 1e-5f);
        }
    }
    __syncthreads();

    int wm = w >> 1, wn = w & 1;
    wmma::fragment<wmma::accumulator, 16, 16, 16, float> acc[2][4];
#pragma unroll
    for (int mi = 0; mi < 2; mi++)
#pragma unroll
        for (int ni = 0; ni < 4; ni++) wmma::fill_fragment(acc[mi][ni], 0.f);

    for (int k0 = 0; k0 < FIN; k0 += 32) {
        // X tile: 128 rows x 32 cols -> Xhi/Xlo
#pragma unroll
        for (int i = 0; i < 4; i++) {
            int e = t + 256 * i;
            int row = e >> 3, c4 = e & 7;
            float4 v = *reinterpret_cast<const float4*>(&X[(size_t)(r0 + row) * FIN + k0 + c4 * 4]);
            if (DO_BN) {
                int cb = k0 + c4 * 4;
                v.x = (v.x - sMU[cb]) * sIS[cb];
                v.y = (v.y - sMU[cb + 1]) * sIS[cb + 1];
                v.z = (v.z - sMU[cb + 2]) * sIS[cb + 2];
                v.w = (v.w - sMU[cb + 3]) * sIS[cb + 3];
            }
            uint32_t h01, l01, h23, l23;
            split_pack(v.x, v.y, h01, l01);
            split_pack(v.z, v.w, h23, l23);
            int idx = row * XLD + c4 * 4;
            *reinterpret_cast<uint32_t*>(&Xhi[idx]) = h01;
            *reinterpret_cast<uint32_t*>(&Xhi[idx + 2]) = h23;
            *reinterpret_cast<uint32_t*>(&Xlo[idx]) = l01;
            *reinterpret_cast<uint32_t*>(&Xlo[idx + 2]) = l23;
        }
        // W tile: 32 rows x 128 cols
        if (PRE) {
#pragma unroll
            for (int i = 0; i < 2; i++) {
                int e = t + 256 * i;          // 0..511 (uint4 units, 8 bf16 each)
                int r = e >> 4, c8 = e & 15;
                uint4 vh = *reinterpret_cast<const uint4*>(&whi_g[(size_t)(k0 + r) * 128 + c8 * 8]);
                uint4 vl = *reinterpret_cast<const uint4*>(&wlo_g[(size_t)(k0 + r) * 128 + c8 * 8]);
                int idx = r * WLD + c8 * 8;
                *reinterpret_cast<uint4*>(&Whi[idx]) = vh;
                *reinterpret_cast<uint4*>(&Wlo[idx]) = vl;
            }
        } else {
#pragma unroll
            for (int i = 0; i < 4; i++) {
                int e = t + 256 * i;
                int r = e >> 5, c4 = e & 31;
                float4 v = *reinterpret_cast<const float4*>(&Wf[(size_t)(k0 + r) * 128 + c4 * 4]);
                uint32_t h01, l01, h23, l23;
                split_pack(v.x, v.y, h01, l01);
                split_pack(v.z, v.w, h23, l23);
                int idx = r * WLD + c4 * 4;
                *reinterpret_cast<uint32_t*>(&Whi[idx]) = h01;
                *reinterpret_cast<uint32_t*>(&Whi[idx + 2]) = h23;
                *reinterpret_cast<uint32_t*>(&Wlo[idx]) = l01;
                *reinterpret_cast<uint32_t*>(&Wlo[idx + 2]) = l23;
            }
        }
        __syncthreads();

#pragma unroll
        for (int kk = 0; kk < 32; kk += 16) {
            wmma::fragment<wmma::matrix_a, 16, 16, 16, __nv_bfloat16, wmma::row_major> ahi[2], alo[2];
            wmma::fragment<wmma::matrix_b, 16, 16, 16, __nv_bfloat16, wmma::row_major> bhi[4], blo[4];
#pragma unroll
            for (int mi = 0; mi < 2; mi++) {
                const __nv_bfloat16* pa = Xhi + (wm * 32 + mi * 16) * XLD + kk;
                wmma::load_matrix_sync(ahi[mi], pa, XLD);
                wmma::load_matrix_sync(alo[mi], pa + 128 * XLD, XLD);
            }
#pragma unroll
            for (int ni = 0; ni < 4; ni++) {
                const __nv_bfloat16* pb = Whi + kk * WLD + wn * 64 + ni * 16;
                wmma::load_matrix_sync(bhi[ni], pb, WLD);
                wmma::load_matrix_sync(blo[ni], pb + 32 * WLD, WLD);
            }
#pragma unroll
            for (int mi = 0; mi < 2; mi++)
#pragma unroll
                for (int ni = 0; ni < 4; ni++) {
                    wmma::mma_sync(acc[mi][ni], ahi[mi], bhi[ni], acc[mi][ni]);
                    wmma::mma_sync(acc[mi][ni], ahi[mi], blo[ni], acc[mi][ni]);
                    wmma::mma_sync(acc[mi][ni], alo[mi], bhi[ni], acc[mi][ni]);
                }
        }
        __syncthreads();
    }

#pragma unroll
    for (int mi = 0; mi < 2; mi++)
#pragma unroll
        for (int ni = 0; ni < 4; ni++)
            wmma::store_matrix_sync(stg + (wm * 32 + mi * 16) * 132 + wn * 64 + ni * 16,
                                    acc[mi][ni], 132, wmma::mem_row_major);
    __syncthreads();

    if (t < 128) {
        const float4* row4 = reinterpret_cast<const float4*>(stg) + t * 33;
        const float4* as4 = reinterpret_cast<const float4*>(sAS);
        const float4* ad4 = reinterpret_cast<const float4*>(sAD);
        float es = 0.f, ed = 0.f;
#pragma unroll
        for (int c = 0; c < 32; c++) {
            float4 v = row4[c];
            float4 a = as4[c];
            float4 d = ad4[c];
            es += v.x * a.x + v.y * a.y + v.z * a.z + v.w * a.w;
            ed += v.x * d.x + v.y * d.y + v.z * d.z + v.w * d.w;
        }
        g_es[r0 + t] = es;
        g_ed[r0 + t] = ed;
    }
#pragma unroll
    for (int i = 0; i < 16; i++) {
        int e4 = t + 256 * i;
        int row = e4 >> 5, c4 = e4 & 31;
        reinterpret_cast<float4*>(&g_h[(size_t)(r0 + row) * 128])[c4] =
            reinterpret_cast<const float4*>(stg + row * 132)[c4];
    }
}

// ---------------- fused aggregate + pool + bias + relu + BN stats ----------------
// warp per pool pair; de-predicated common loop + tails for max load batching.
__global__ void __launch_bounds__(256) aggregate_pool_kernel(
        int cbase, const float* __restrict__ bias,
        float* __restrict__ sums, float* __restrict__ sumsq) {
    __shared__ int sh_s[8][2 * CAP];
    __shared__ float sh_w[8][2 * CAP];
    __shared__ float psum[8][128];
    __shared__ float psq[8][128];
    int t = threadIdx.x;
    int wp = t >> 5;
    int lane = t & 31;
    int j = blockIdx.x * 8 + wp;
    int a = 2 * j, b = a + 1;

    int na = min(g_cnt[cbase + a], CAP);
    int nb = min(g_cnt[cbase + b], CAP);
    int base_a = (cbase + a) * CAP;
    int base_b = (cbase + b) * CAP;
    float ed_a = g_ed[a], ed_b = g_ed[b];
    float sl_a = lrelu(g_es[a] + ed_a);
    float sl_b = lrelu(g_es[b] + ed_b);

    float mxa = sl_a, mxb = sl_b;
    for (int i = lane; i < na; i += 32) {
        int s = g_adj[base_a + i];
        float lg = lrelu(g_es[s] + ed_a);
        sh_s[wp][i] = s;
        sh_w[wp][i] = lg;
        mxa = fmaxf(mxa, lg);
    }
    for (int i = lane; i < nb; i += 32) {
        int s = g_adj[base_b + i];
        float lg = lrelu(g_es[s] + ed_b);
        sh_s[wp][CAP + i] = s;
        sh_w[wp][CAP + i] = lg;
        mxb = fmaxf(mxb, lg);
    }
#pragma unroll
    for (int o = 16; o; o >>= 1) {
        mxa = fmaxf(mxa, __shfl_xor_sync(0xffffffffu, mxa, o));
        mxb = fmaxf(mxb, __shfl_xor_sync(0xffffffffu, mxb, o));
    }
    __syncwarp();
    for (int i = lane; i < na; i += 32) sh_w[wp][i] = __expf(sh_w[wp][i] - mxa);
    for (int i = lane; i < nb; i += 32) sh_w[wp][CAP + i] = __expf(sh_w[wp][CAP + i] - mxb);
    __syncwarp();

    const float4* h4 = reinterpret_cast<const float4*>(g_h);
    float wsa = __expf(sl_a - mxa);
    float wsb = __expf(sl_b - mxb);
    float4 ha = h4[a * 32 + lane];
    float4 hb = h4[b * 32 + lane];
    float4 accA = make_float4(wsa * ha.x, wsa * ha.y, wsa * ha.z, wsa * ha.w);
    float4 accB = make_float4(wsb * hb.x, wsb * hb.y, wsb * hb.z, wsb * hb.w);
    float denA = wsa, denB = wsb;

    int nc = min(na, nb);
    int k = 0;
#pragma unroll 4
    for (; k < nc; k++) {
        int sA = sh_s[wp][k];
        int sB = sh_s[wp][CAP + k];
        float wA = sh_w[wp][k];
        float wB = sh_w[wp][CAP + k];
        float4 hA = h4[sA * 32 + lane];
        float4 hB = h4[sB * 32 + lane];
        denA += wA; denB += wB;
        accA.x += wA * hA.x; accA.y += wA * hA.y; accA.z += wA * hA.z; accA.w += wA * hA.w;
        accB.x += wB * hB.x; accB.y += wB * hB.y; accB.z += wB * hB.z; accB.w += wB * hB.w;
    }
#pragma unroll 2
    for (; k < na; k++) {
        int sA = sh_s[wp][k];
        float wA = sh_w[wp][k];
        float4 hA = h4[sA * 32 + lane];
        denA += wA;
        accA.x += wA * hA.x; accA.y += wA * hA.y; accA.z += wA * hA.z; accA.w += wA * hA.w;
    }
#pragma unroll 2
    for (; k < nb; k++) {
        int sB = sh_s[wp][CAP + k];
        float wB = sh_w[wp][CAP + k];
        float4 hB = h4[sB * 32 + lane];
        denB += wB;
        accB.x += wB * hB.x; accB.y += wB * hB.y; accB.z += wB * hB.z; accB.w += wB * hB.w;
    }

    float iA = 1.f / denA, iB = 1.f / denB;
    float4 bv = reinterpret_cast<const float4*>(bias)[lane];
    float4 v;
    v.x = fmaxf(fmaxf(accA.x * iA, accB.x * iB) + bv.x, 0.f);
    v.y = fmaxf(fmaxf(accA.y * iA, accB.y * iB) + bv.y, 0.f);
    v.z = fmaxf(fmaxf(accA.z * iA, accB.z * iB) + bv.z, 0.f);
    v.w = fmaxf(fmaxf(accA.w * iA, accB.w * iB) + bv.w, 0.f);
    reinterpret_cast<float4*>(g_x)[j * 32 + lane] = v;

    *reinterpret_cast<float4*>(&psum[wp][lane * 4]) = v;
    *reinterpret_cast<float4*>(&psq[wp][lane * 4]) =
        make_float4(v.x * v.x, v.y * v.y, v.z * v.z, v.w * v.w);
    __syncthreads();
    if (t < 128) {
        float s = 0.f, q = 0.f;
#pragma unroll
        for (int w2 = 0; w2 < 8; w2++) { s += psum[w2][t]; q += psq[w2][t]; }
        atomicAdd(&sums[t], s);
        atomicAdd(&sumsq[t], q);
    }
}

__global__ void bn_apply_kernel(int Mout, float* __restrict__ outp,
                                const float* __restrict__ sums, const float* __restrict__ sumsq) {
    int idx = blockIdx.x * blockDim.x + threadIdx.x;
    if (idx >= Mout * 128) return;
    int c = idx & 127;
    float inv = 1.f / (float)Mout;
    float mu = sums[c] * inv;
    float var = sumsq[c] * inv - mu * mu;
    outp[idx] = (g_x[idx] - mu) * rsqrtf(var + 1e-5f);
}

// ---------------- launch ----------------
extern "C" void kernel_launch(void* const* d_in, const int* in_sizes, int n_in,
                              void* d_out, int out_size) {
    const float* x    = (const float*)d_in[0];
    const float* W0   = (const float*)d_in[1];
    const float* W1   = (const float*)d_in[2];
    const float* W2   = (const float*)d_in[3];
    const float* as_  = (const float*)d_in[4];
    const float* ad_  = (const float*)d_in[5];
    const float* bias = (const float*)d_in[6];
    const int*   ei   = (const int*)d_in[7];
    float* out = (float*)d_out;

    float* sum_p; float* ssq_p;
    cudaGetSymbolAddress((void**)&sum_p, g_sum);
    cudaGetSymbolAddress((void**)&ssq_p, g_sumsq);
    __nv_bfloat16* whi_p; __nv_bfloat16* wlo_p;
    cudaGetSymbolAddress((void**)&whi_p, g_whi);
    cudaGetSymbolAddress((void**)&wlo_p, g_wlo);

    cudaFuncSetAttribute(tgemm_att_kernel<64, false, false>,
                         cudaFuncAttributeMaxDynamicSharedMemorySize, GEMM_SMEM);
    cudaFuncSetAttribute(tgemm_att_kernel<128, true, true>,
                         cudaFuncAttributeMaxDynamicSharedMemorySize, GEMM_SMEM);

    static cudaStream_t side = nullptr;
    static cudaEvent_t e0 = nullptr, e1 = nullptr;
    if (!side) {
        cudaStreamCreateWithFlags(&side, cudaStreamNonBlocking);
        cudaEventCreateWithFlags(&e0, cudaEventDisableTiming);
        cudaEventCreateWithFlags(&e1, cudaEventDisableTiming);
    }

    // fork: W pre-split + CSR build on side stream, concurrent with layer-0 GEMM
    cudaEventRecord(e0, 0);
    cudaStreamWaitEvent(side, e0, 0);
    wsplit_kernel<<<(128 * 128) / 256, 256, 0, side>>>(W1, whi_p, wlo_p);
    wsplit_kernel<<<(128 * 128) / 256, 256, 0, side>>>(W2, whi_p + 128 * 128, wlo_p + 128 * 128);
    clear_kernel<<<(BM_TOT + 255) / 256, 256, 0, side>>>();
    build_csr_kernel<<<E0 / 256, 256, 0, side>>>(ei);
    cudaEventRecord(e1, side);

    // layer 0 (W0 converted inline)
    tgemm_att_kernel<64, false, false><<<M0 / 128, 256, GEMM_SMEM>>>(
        x, W0, nullptr, nullptr, as_, ad_, nullptr, nullptr, 0.f);
    cudaStreamWaitEvent(0, e1, 0);
    aggregate_pool_kernel<<<16384 / 8, 256>>>(0, bias, sum_p, ssq_p);

    // layer 1 (pre-split W1)
    tgemm_att_kernel<128, true, true><<<16384 / 128, 256, GEMM_SMEM>>>(
        nullptr, nullptr, whi_p, wlo_p, as_ + 128, ad_ + 128, sum_p, ssq_p, 1.f / 16384.f);
    aggregate_pool_kernel<<<8192 / 8, 256>>>(M0, bias + 128, sum_p + 128, ssq_p + 128);

    // layer 2 (pre-split W2)
    tgemm_att_kernel<128, true, true><<<8192 / 128, 256, GEMM_SMEM>>>(
        nullptr, nullptr, whi_p + 128 * 128, wlo_p + 128 * 128,
        as_ + 256, ad_ + 256, sum_p + 128, ssq_p + 128, 1.f / 8192.f);
    aggregate_pool_kernel<<<4096 / 8, 256>>>(M0 + M0 / 2, bias + 256, sum_p + 256, ssq_p + 256);

    // final BN -> output
    bn_apply_kernel<<<(4096 * 128) / 256, 256>>>(4096, out, sum_p + 256, ssq_p + 256);
}